// round 13
// baseline (speedup 1.0000x reference)
#include <cuda_runtime.h>
#include <cuda_fp16.h>
#include <math.h>
#include <stdint.h>

#define NROW 8192
#define DIM 1024
#define DIM2 512
#define BM 128
#define BN 128
#define NCT (NROW / BN)            // 64 partial slots
#define NTILE 2080                 // 64*65/2 upper-triangle tiles
#define NOFFD 2016                 // strictly-upper tiles
#define BIGF 9999999.0f
#define MARGINF 0.3f

#define STAGE_BYTES 32768          // A (128x128B) + B (128x128B), K=64 halfs
#define B_OFF 16384
#define NSTG 3
#define SMEM_TOTAL (NSTG * STAGE_BYTES)   // 96 KB
#define NSTAGES_K 16               // 1024 / 64

// ---------------- device scratch ----------------
__device__ int   g_lab64;
__device__ float g_sq[NROW];
__device__ float g_nrm[NROW];
__device__ __half g_hi[(size_t)NROW * DIM];
__device__ float g_p1v[NCT][NROW];
__device__ float g_p2v[NCT][NROW];
__device__ int   g_p1i[NCT][NROW];
__device__ int   g_p2i[NCT][NROW];
__device__ float g_pmn[NCT][NROW];
__device__ float g_ap1[NROW], g_ap2[NROW], g_an[NROW];
__device__ float g_a1[NROW], g_a2[NROW];
__device__ float g_fin[32][3];

// ---------------- helpers ----------------
__device__ __forceinline__ uint32_t smem_u32(const void* p) {
    uint32_t a;
    asm("{ .reg .u64 t; cvta.to.shared.u64 t, %1; cvt.u32.u64 %0, t; }" : "=r"(a) : "l"(p));
    return a;
}
__device__ __forceinline__ void cpasync16(uint32_t dst, const void* src) {
    asm volatile("cp.async.cg.shared.global [%0], [%1], 16;" :: "r"(dst), "l"(src));
}
#define CP_COMMIT() asm volatile("cp.async.commit_group;" ::: "memory")
#define CP_WAIT1()  asm volatile("cp.async.wait_group 1;" ::: "memory")
#define CP_WAIT0()  asm volatile("cp.async.wait_group 0;" ::: "memory")

#define LDM4(r, addr) \
    asm volatile("ldmatrix.sync.aligned.m8n8.x4.shared.b16 {%0,%1,%2,%3}, [%4];" \
        : "=r"((r)[0]), "=r"((r)[1]), "=r"((r)[2]), "=r"((r)[3]) : "r"(addr))

#define MMA16816(c, a, b0_, b1_) \
    asm volatile("mma.sync.aligned.m16n8k16.row.col.f32.f16.f16.f32 " \
        "{%0,%1,%2,%3}, {%4,%5,%6,%7}, {%8,%9}, {%0,%1,%2,%3};" \
        : "+f"((c)[0]), "+f"((c)[1]), "+f"((c)[2]), "+f"((c)[3]) \
        : "r"((a)[0]), "r"((a)[1]), "r"((a)[2]), "r"((a)[3]), "r"(b0_), "r"(b1_))

__device__ __forceinline__ int getlab(const void* lab, int i, int is64) {
    if (is64) return (int)((const long long*)lab)[i];
    return ((const int*)lab)[i];
}
__device__ __forceinline__ bool keybetter(float av, int ai, float bv, int bi) {
    return (av > bv) || (av == bv && ai < bi);
}
__device__ __forceinline__ uint32_t sw128(uint32_t off) { return off ^ ((off >> 3) & 0x70u); }

__device__ __forceinline__ void merge2(float& v1, int& i1, float& v2, int& i2,
                                       float o1v, int o1i, float o2v, int o2i) {
    if (keybetter(o1v, o1i, v1, i1)) {
        if (keybetter(v1, i1, o2v, o2i)) { v2 = v1; i2 = i1; }
        else                             { v2 = o2v; i2 = o2i; }
        v1 = o1v; i1 = o1i;
    } else if (keybetter(o1v, o1i, v2, i2)) { v2 = o1v; i2 = o1i; }
}

// ---------------- kernel 1: fused detect + norms + fp16 convert ----------------
__global__ void k_prep(const float* __restrict__ emb, const float* __restrict__ clot,
                       const void* __restrict__ lab) {
    int r = blockIdx.x, t = threadIdx.x;
    int lane = t & 31, w = t >> 5;
    if (r == 0 && t == 0) {
        const unsigned* p = (const unsigned*)lab;
        int is64 = 1;
        for (int i = 0; i < 64; i++) if (p[2 * i + 1] != 0u) { is64 = 0; break; }
        g_lab64 = is64;
    }
    float4 v = ((const float4*)(emb + (size_t)r * DIM))[t];
    float s = v.x * v.x + v.y * v.y + v.z * v.z + v.w * v.w;
    size_t o = (size_t)r * DIM + t * 4;
    *(__half2*)(g_hi + o)     = __half2(__float2half(v.x), __float2half(v.y));
    *(__half2*)(g_hi + o + 2) = __half2(__float2half(v.z), __float2half(v.w));
    float c = 0.f;
    if (t < DIM2 / 4) {
        float4 wv = ((const float4*)(clot + (size_t)r * DIM2))[t];
        c = wv.x * wv.x + wv.y * wv.y + wv.z * wv.z + wv.w * wv.w;
    }
    #pragma unroll
    for (int o2 = 16; o2 > 0; o2 >>= 1) {
        s += __shfl_xor_sync(0xffffffffu, s, o2);
        c += __shfl_xor_sync(0xffffffffu, c, o2);
    }
    __shared__ float se[8], sc[8];
    if (lane == 0) { se[w] = s; sc[w] = c; }
    __syncthreads();
    if (t == 0) {
        float ss = 0.f, cc = 0.f;
        #pragma unroll
        for (int i = 0; i < 8; i++) { ss += se[i]; cc += sc[i]; }
        g_sq[r] = ss; g_nrm[r] = sqrtf(cc);
    }
}

// ---------------- kernel 2: fp16 HMMA GEMM, 4 warps x 64x64 warp tiles ----------------
__global__ __launch_bounds__(128, 2) void k_dist_mma(const void* __restrict__ lab) {
    extern __shared__ char smem[];
    const uint32_t sb = smem_u32(smem);
    const int tid = threadIdx.x;
    const int lane = tid & 31, wid = tid >> 5;
    const int wm = wid >> 1, wn = wid & 1;
    const int lab64 = g_lab64;

    // tile id -> (rb, cb): ids [0,2016) strictly-upper, [2016,2080) diagonal (run last)
    int rb, cb;
    if (blockIdx.x < NOFFD) {
        int u = blockIdx.x; rb = 0;
        while (u >= 63 - rb) { u -= 63 - rb; rb++; }
        cb = rb + 1 + u;
    } else {
        rb = cb = blockIdx.x - NOFFD;
    }
    const int r0 = rb * BM, c0 = cb * BN;

    // ---- loader: thread t owns (row = (t>>3)+16v, seg = t&7) for A and B ----
    const int lrow = tid >> 3, lseg = tid & 7;
    const char* aSrc = (const char*)(g_hi + (size_t)(r0 + lrow) * DIM + lseg * 8);
    const char* bSrc = (const char*)(g_hi + (size_t)(c0 + lrow) * DIM + lseg * 8);
    const uint32_t dstA0 = sw128((uint32_t)lrow * 128u + (uint32_t)lseg * 16u);
    const uint32_t dstB0 = (uint32_t)B_OFF + dstA0;   // same swizzle pattern, B region
    const size_t rowStep = (size_t)16 * DIM * 2;      // +16 rows in source

    // ---- ldmatrix pre-offsets + row-dependent swizzle masks (128B rows) ----
    uint32_t preA[4], mskA[4], preB[4], mskB[4];
    {
        int rA = wm * 64 + (lane & 15);
        int sA = lane >> 4;
        #pragma unroll
        for (int mt = 0; mt < 4; mt++) {
            uint32_t p = (uint32_t)(rA + mt * 16) * 128u + (uint32_t)sA * 16u;
            mskA[mt] = (p >> 3) & 0x70u;
            preA[mt] = p;
        }
        int rB = wn * 64 + ((lane >> 4) << 3) + (lane & 7);
        int sB = (lane >> 3) & 1;
        #pragma unroll
        for (int np = 0; np < 4; np++) {
            uint32_t p = (uint32_t)(rB + np * 16) * 128u + (uint32_t)sB * 16u;
            mskB[np] = (p >> 3) & 0x70u;
            preB[np] = p;
        }
    }

    float acc[4][8][4];
    #pragma unroll
    for (int a = 0; a < 4; a++)
        #pragma unroll
        for (int b = 0; b < 8; b++)
            #pragma unroll
            for (int c = 0; c < 4; c++) acc[a][b][c] = 0.f;

    // ---- prologue: fill 2 stages ----
    #pragma unroll
    for (int p = 0; p < 2; p++) {
        uint32_t db = sb + (uint32_t)p * STAGE_BYTES;
        const char* as = aSrc + (size_t)p * 128;
        const char* bs = bSrc + (size_t)p * 128;
        #pragma unroll
        for (int v = 0; v < 8; v++) {
            cpasync16(db + dstA0 + v * 2048u, as + v * rowStep);
            cpasync16(db + dstB0 + v * 2048u, bs + v * rowStep);
        }
        CP_COMMIT();
    }

    // ---- main loop: 16 K-stages of 64; ring of 3 ----
    int buf = 0, pbuf = 2;
    for (int s = 0; s < NSTAGES_K; s++) {
        CP_WAIT1();
        __syncthreads();
        {
            int sn = s + 2;
            if (sn < NSTAGES_K) {
                uint32_t db = sb + (uint32_t)pbuf * STAGE_BYTES;
                const char* as = aSrc + (size_t)sn * 128;
                const char* bs = bSrc + (size_t)sn * 128;
                #pragma unroll
                for (int v = 0; v < 8; v++) {
                    cpasync16(db + dstA0 + v * 2048u, as + v * rowStep);
                    cpasync16(db + dstB0 + v * 2048u, bs + v * rowStep);
                }
            }
            CP_COMMIT();
        }
        const uint32_t base = sb + (uint32_t)buf * STAGE_BYTES;
        const uint32_t baseB = base + B_OFF;
        if (++buf == NSTG) buf = 0;
        if (++pbuf == NSTG) pbuf = 0;

        #pragma unroll
        for (int kc = 0; kc < 4; kc++) {
            const uint32_t kd = (uint32_t)kc * 32u;
            uint32_t BH[4][4];
            #pragma unroll
            for (int np = 0; np < 4; np++)
                LDM4(BH[np], baseB + ((preB[np] + kd) ^ mskB[np]));
            uint32_t AH[4][4];
            #pragma unroll
            for (int mt = 0; mt < 4; mt++)
                LDM4(AH[mt], base + ((preA[mt] + kd) ^ mskA[mt]));
            #pragma unroll
            for (int mt = 0; mt < 4; mt++)
                #pragma unroll
                for (int nt = 0; nt < 8; nt++)
                    MMA16816(acc[mt][nt], AH[mt], BH[nt >> 1][(nt & 1) * 2], BH[nt >> 1][(nt & 1) * 2 + 1]);
        }
    }
    CP_WAIT0();
    __syncthreads();   // ring dead; smem reused below

    const int tg = lane & 3, g = lane >> 2;
    float sqj[16]; int labj[16];
    #pragma unroll
    for (int ln = 0; ln < 16; ln++) {
        int cc = c0 + wn * 64 + (ln >> 1) * 8 + tg * 2 + (ln & 1);
        sqj[ln] = g_sq[cc];
        labj[ln] = getlab(lab, cc, lab64);
    }
    float sqi[8]; int labi[8];
    #pragma unroll
    for (int lm = 0; lm < 8; lm++) {
        int m = r0 + wm * 64 + (lm >> 1) * 16 + g + (lm & 1) * 8;
        sqi[lm] = g_sq[m];
        labi[lm] = getlab(lab, m, lab64);
    }

    // smem overlays: [128][2]
    float* sv1 = (float*)smem;
    float* sv2 = (float*)(smem + 1024);
    float* smn = (float*)(smem + 2048);
    int*   si1 = (int*)(smem + 3072);
    int*   si2 = (int*)(smem + 4096);
    float* cv1 = (float*)(smem + 5120);
    float* cv2 = (float*)(smem + 6144);
    float* cmn = (float*)(smem + 7168);
    int*   ci1 = (int*)(smem + 8192);
    int*   ci2 = (int*)(smem + 9216);

    // ======== row stats (d^2 domain; d^2 stored back into acc for col pass) ========
    {
        float b1v[8], b2v[8], mnv[8]; int b1i[8], b2i[8];
        #pragma unroll
        for (int lm = 0; lm < 8; lm++) {
            float v1 = -INFINITY, v2 = -INFINITY, mn = INFINITY;
            int i1 = 0x7fffffff, i2 = 0x7fffffff;
            #pragma unroll
            for (int ln = 0; ln < 16; ln++) {
                int col = c0 + wn * 64 + (ln >> 1) * 8 + tg * 2 + (ln & 1);
                float& ar = acc[lm >> 1][ln >> 1][(lm & 1) * 2 + (ln & 1)];
                float d2 = fmaf(-2.0f, ar, sqi[lm] + sqj[ln]);
                ar = d2;
                bool same = (labi[lm] == labj[ln]);
                float pv = same ? d2 : d2 - BIGF;
                float nv = same ? d2 + BIGF : d2;
                mn = fminf(mn, nv);
                if (keybetter(pv, col, v1, i1)) { v2 = v1; i2 = i1; v1 = pv; i1 = col; }
                else if (keybetter(pv, col, v2, i2)) { v2 = pv; i2 = col; }
            }
            b1v[lm] = v1; b1i[lm] = i1; b2v[lm] = v2; b2i[lm] = i2; mnv[lm] = mn;
        }
        #pragma unroll
        for (int lm = 0; lm < 8; lm++) {
            #pragma unroll
            for (int off = 1; off <= 2; off <<= 1) {
                float o1v = __shfl_xor_sync(0xffffffffu, b1v[lm], off);
                int   o1i = __shfl_xor_sync(0xffffffffu, b1i[lm], off);
                float o2v = __shfl_xor_sync(0xffffffffu, b2v[lm], off);
                int   o2i = __shfl_xor_sync(0xffffffffu, b2i[lm], off);
                float omn = __shfl_xor_sync(0xffffffffu, mnv[lm], off);
                mnv[lm] = fminf(mnv[lm], omn);
                merge2(b1v[lm], b1i[lm], b2v[lm], b2i[lm], o1v, o1i, o2v, o2i);
            }
        }
        if (tg == 0) {
            #pragma unroll
            for (int lm = 0; lm < 8; lm++) {
                int rl = wm * 64 + (lm >> 1) * 16 + g + (lm & 1) * 8;
                sv1[rl * 2 + wn] = b1v[lm]; si1[rl * 2 + wn] = b1i[lm];
                sv2[rl * 2 + wn] = b2v[lm]; si2[rl * 2 + wn] = b2i[lm];
                smn[rl * 2 + wn] = mnv[lm];
            }
        }
    }

    // ======== col stats (transposed harvest; skip on diagonal) ========
    if (rb != cb) {
        float b1v[16], b2v[16], mnv[16]; int b1i[16], b2i[16];
        #pragma unroll
        for (int ln = 0; ln < 16; ln++) {
            float v1 = -INFINITY, v2 = -INFINITY, mn = INFINITY;
            int i1 = 0x7fffffff, i2 = 0x7fffffff;
            #pragma unroll
            for (int lm = 0; lm < 8; lm++) {
                int rowidx = r0 + wm * 64 + (lm >> 1) * 16 + g + (lm & 1) * 8;
                float d2 = acc[lm >> 1][ln >> 1][(lm & 1) * 2 + (ln & 1)];
                bool same = (labi[lm] == labj[ln]);
                float pv = same ? d2 : d2 - BIGF;
                float nv = same ? d2 + BIGF : d2;
                mn = fminf(mn, nv);
                if (keybetter(pv, rowidx, v1, i1)) { v2 = v1; i2 = i1; v1 = pv; i1 = rowidx; }
                else if (keybetter(pv, rowidx, v2, i2)) { v2 = pv; i2 = rowidx; }
            }
            b1v[ln] = v1; b1i[ln] = i1; b2v[ln] = v2; b2i[ln] = i2; mnv[ln] = mn;
        }
        #pragma unroll
        for (int ln = 0; ln < 16; ln++) {
            #pragma unroll
            for (int off = 4; off <= 16; off <<= 1) {
                float o1v = __shfl_xor_sync(0xffffffffu, b1v[ln], off);
                int   o1i = __shfl_xor_sync(0xffffffffu, b1i[ln], off);
                float o2v = __shfl_xor_sync(0xffffffffu, b2v[ln], off);
                int   o2i = __shfl_xor_sync(0xffffffffu, b2i[ln], off);
                float omn = __shfl_xor_sync(0xffffffffu, mnv[ln], off);
                mnv[ln] = fminf(mnv[ln], omn);
                merge2(b1v[ln], b1i[ln], b2v[ln], b2i[ln], o1v, o1i, o2v, o2i);
            }
        }
        if (g == 0) {
            #pragma unroll
            for (int ln = 0; ln < 16; ln++) {
                int cl = wn * 64 + (ln >> 1) * 8 + tg * 2 + (ln & 1);
                cv1[cl * 2 + wm] = b1v[ln]; ci1[cl * 2 + wm] = b1i[ln];
                cv2[cl * 2 + wm] = b2v[ln]; ci2[cl * 2 + wm] = b2i[ln];
                cmn[cl * 2 + wm] = mnv[ln];
            }
        }
    }
    __syncthreads();

    // final merges + global writes (128 threads = 128 rows/cols)
    {
        {
            float v1 = -INFINITY, v2 = -INFINITY, mn = INFINITY;
            int i1 = 0x7fffffff, i2 = 0x7fffffff;
            #pragma unroll
            for (int w = 0; w < 2; w++) {
                mn = fminf(mn, smn[tid * 2 + w]);
                merge2(v1, i1, v2, i2, sv1[tid * 2 + w], si1[tid * 2 + w], sv2[tid * 2 + w], si2[tid * 2 + w]);
            }
            int r = r0 + tid;
            g_p1v[cb][r] = v1; g_p1i[cb][r] = i1;
            g_p2v[cb][r] = v2; g_p2i[cb][r] = i2;
            g_pmn[cb][r] = mn;
        }
        if (rb != cb) {
            float v1 = -INFINITY, v2 = -INFINITY, mn = INFINITY;
            int i1 = 0x7fffffff, i2 = 0x7fffffff;
            #pragma unroll
            for (int w = 0; w < 2; w++) {
                mn = fminf(mn, cmn[tid * 2 + w]);
                merge2(v1, i1, v2, i2, cv1[tid * 2 + w], ci1[tid * 2 + w], cv2[tid * 2 + w], ci2[tid * 2 + w]);
            }
            int r = c0 + tid;
            g_p1v[rb][r] = v1; g_p1i[rb][r] = i1;
            g_p2v[rb][r] = v2; g_p2i[rb][r] = i2;
            g_pmn[rb][r] = mn;
        }
    }
}

// ---------------- kernel 3: fused warp-per-row merge + d^2->dist + cos dots ----------------
__global__ void k_merge_alpha(const float* __restrict__ clot) {
    int t = threadIdx.x;
    int r = blockIdx.x * 8 + (t >> 5);
    int l = t & 31;
    float b1v = g_p1v[l][r]; int b1i = g_p1i[l][r];
    float b2v = g_p2v[l][r]; int b2i = g_p2i[l][r];
    float mn  = g_pmn[l][r];
    int c2 = l + 32;
    mn = fminf(mn, g_pmn[c2][r]);
    merge2(b1v, b1i, b2v, b2i, g_p1v[c2][r], g_p1i[c2][r], g_p2v[c2][r], g_p2i[c2][r]);
    #pragma unroll
    for (int off = 16; off > 0; off >>= 1) {
        float o1v = __shfl_xor_sync(0xffffffffu, b1v, off);
        int   o1i = __shfl_xor_sync(0xffffffffu, b1i, off);
        float o2v = __shfl_xor_sync(0xffffffffu, b2v, off);
        int   o2i = __shfl_xor_sync(0xffffffffu, b2i, off);
        float omn = __shfl_xor_sync(0xffffffffu, mn,  off);
        mn = fminf(mn, omn);
        merge2(b1v, b1i, b2v, b2i, o1v, o1i, o2v, o2i);
    }
    int j1 = b1i, j2 = b2i;
    const float* cr = clot + (size_t)r * DIM2;
    const float* ca = clot + (size_t)j1 * DIM2;
    const float* cb = clot + (size_t)j2 * DIM2;
    float d1 = 0.f, d2 = 0.f;
    #pragma unroll 4
    for (int k = l; k < DIM2; k += 32) {
        float c = cr[k];
        d1 = fmaf(c, ca[k], d1);
        d2 = fmaf(c, cb[k], d2);
    }
    #pragma unroll
    for (int o = 16; o > 0; o >>= 1) {
        d1 += __shfl_xor_sync(0xffffffffu, d1, o);
        d2 += __shfl_xor_sync(0xffffffffu, d2, o);
    }
    if (l == 0) {
        float ap1 = (b1v < -1e6f) ? (sqrtf(fmaxf(b1v + BIGF, 1e-12f)) - BIGF)
                                  : sqrtf(fmaxf(b1v, 1e-12f));
        float ap2 = (b2v < -1e6f) ? (sqrtf(fmaxf(b2v + BIGF, 1e-12f)) - BIGF)
                                  : sqrtf(fmaxf(b2v, 1e-12f));
        float an  = (mn > 1e6f) ? (sqrtf(fmaxf(mn - BIGF, 1e-12f)) + BIGF)
                                : sqrtf(fmaxf(mn, 1e-12f));
        g_ap1[r] = ap1; g_ap2[r] = ap2; g_an[r] = an;
        g_a1[r] = d1 / (g_nrm[r] * g_nrm[j1]);
        g_a2[r] = d2 / (g_nrm[r] * g_nrm[j2]);
    }
}

// ---------------- kernel 4a: per-block loss partials ----------------
__global__ void k_final_part() {
    int t = threadIdx.x;
    int r = blockIdx.x * 256 + t;
    float ap1 = g_ap1[r], ap2 = g_ap2[r], an = g_an[r];
    float a1 = g_a1[r], a2 = g_a2[r];
    float y  = (a1 < a2) ? -1.f : 1.f;
    float ym = (a1 == a2) ? 0.f : 1.f;
    float x1 = ap2 * ym;
    float x2 = ap1 * ym + MARGINF * (a1 - a2 - y);
    float t11 = fmaxf(0.f, -y * (x1 - x2) + MARGINF);
    float ap1m = ap1 + MARGINF * (a1 - 1.f);
    float t13 = fmaxf(0.f, -(an - ap1m) + MARGINF);
    float tp = (an > ap1m) ? 1.f : 0.f;
    #pragma unroll
    for (int o = 16; o > 0; o >>= 1) {
        t11 += __shfl_xor_sync(0xffffffffu, t11, o);
        t13 += __shfl_xor_sync(0xffffffffu, t13, o);
        tp  += __shfl_xor_sync(0xffffffffu, tp,  o);
    }
    __shared__ float s1[8], s2[8], s3[8];
    int w = t >> 5, l = t & 31;
    if (l == 0) { s1[w] = t11; s2[w] = t13; s3[w] = tp; }
    __syncthreads();
    if (t == 0) {
        float a = 0.f, b = 0.f, c = 0.f;
        #pragma unroll
        for (int i = 0; i < 8; i++) { a += s1[i]; b += s2[i]; c += s3[i]; }
        g_fin[blockIdx.x][0] = a;
        g_fin[blockIdx.x][1] = b;
        g_fin[blockIdx.x][2] = c;
    }
}

// ---------------- kernel 4b: combine 32 partials ----------------
__global__ void k_final2(float* __restrict__ out) {
    int t = threadIdx.x;  // 32 threads
    float a = g_fin[t][0], b = g_fin[t][1], c = g_fin[t][2];
    #pragma unroll
    for (int o = 16; o > 0; o >>= 1) {
        a += __shfl_xor_sync(0xffffffffu, a, o);
        b += __shfl_xor_sync(0xffffffffu, b, o);
        c += __shfl_xor_sync(0xffffffffu, c, o);
    }
    if (t == 0) {
        out[0] = 0.1f * (a / (float)NROW) + (b / (float)NROW);
        out[1] = c / (float)NROW;
    }
}

// ---------------- launch ----------------
extern "C" void kernel_launch(void* const* d_in, const int* in_sizes, int n_in,
                              void* d_out, int out_size) {
    const float* emb  = (const float*)d_in[0];
    const void*  lab  = d_in[1];
    const float* clot = (const float*)d_in[2];
    float* out = (float*)d_out;

    cudaFuncSetAttribute(k_dist_mma, cudaFuncAttributeMaxDynamicSharedMemorySize, SMEM_TOTAL);

    k_prep<<<NROW, 256>>>(emb, clot, lab);
    k_dist_mma<<<NTILE, 128, SMEM_TOTAL>>>(lab);
    k_merge_alpha<<<NROW / 8, 256>>>(clot);
    k_final_part<<<32, 256>>>();
    k_final2<<<1, 32>>>(out);
}

// round 14
// speedup vs baseline: 1.2486x; 1.2486x over previous
#include <cuda_runtime.h>
#include <cuda_fp16.h>
#include <math.h>
#include <stdint.h>

#define NROW 8192
#define DIM 1024
#define DIM2 512
#define BM 128
#define BN 128
#define NCT (NROW / BN)            // 64 partial slots
#define NTILE 2080                 // 64*65/2 upper-triangle tiles
#define NOFFD 2016                 // strictly-upper tiles
#define BIGF 9999999.0f
#define MARGINF 0.3f

#define STAGE_BYTES 32768          // A (128x128B) + B (128x128B), K=64 halfs
#define B_OFF 16384
#define NSTG 3
#define SMEM_TOTAL (NSTG * STAGE_BYTES)   // 96 KB
#define NSTAGES_K 16               // 1024 / 64

// ---------------- device scratch ----------------
__device__ int   g_lab64;
__device__ float g_sq[NROW];
__device__ float g_nrm[NROW];
__device__ __half g_hi[(size_t)NROW * DIM];
__device__ float g_p1v[NCT][NROW];
__device__ float g_p2v[NCT][NROW];
__device__ int   g_p1i[NCT][NROW];
__device__ int   g_p2i[NCT][NROW];
__device__ float g_pmn[NCT][NROW];
__device__ float g_ap1[NROW], g_ap2[NROW], g_an[NROW];
__device__ float g_a1[NROW], g_a2[NROW];
__device__ float g_fin[32][3];

// ---------------- helpers ----------------
__device__ __forceinline__ uint32_t smem_u32(const void* p) {
    uint32_t a;
    asm("{ .reg .u64 t; cvta.to.shared.u64 t, %1; cvt.u32.u64 %0, t; }" : "=r"(a) : "l"(p));
    return a;
}
__device__ __forceinline__ void cpasync16(uint32_t dst, const void* src) {
    asm volatile("cp.async.cg.shared.global [%0], [%1], 16;" :: "r"(dst), "l"(src));
}
#define CP_COMMIT() asm volatile("cp.async.commit_group;" ::: "memory")
#define CP_WAIT1()  asm volatile("cp.async.wait_group 1;" ::: "memory")
#define CP_WAIT0()  asm volatile("cp.async.wait_group 0;" ::: "memory")

#define LDM4(r, addr) \
    asm volatile("ldmatrix.sync.aligned.m8n8.x4.shared.b16 {%0,%1,%2,%3}, [%4];" \
        : "=r"((r)[0]), "=r"((r)[1]), "=r"((r)[2]), "=r"((r)[3]) : "r"(addr))

#define MMA16816(c, a, b0_, b1_) \
    asm volatile("mma.sync.aligned.m16n8k16.row.col.f32.f16.f16.f32 " \
        "{%0,%1,%2,%3}, {%4,%5,%6,%7}, {%8,%9}, {%0,%1,%2,%3};" \
        : "+f"((c)[0]), "+f"((c)[1]), "+f"((c)[2]), "+f"((c)[3]) \
        : "r"((a)[0]), "r"((a)[1]), "r"((a)[2]), "r"((a)[3]), "r"(b0_), "r"(b1_))

__device__ __forceinline__ int getlab(const void* lab, int i, int is64) {
    if (is64) return (int)((const long long*)lab)[i];
    return ((const int*)lab)[i];
}
__device__ __forceinline__ bool keybetter(float av, int ai, float bv, int bi) {
    return (av > bv) || (av == bv && ai < bi);
}
__device__ __forceinline__ uint32_t sw128(uint32_t off) { return off ^ ((off >> 3) & 0x70u); }

__device__ __forceinline__ void merge2(float& v1, int& i1, float& v2, int& i2,
                                       float o1v, int o1i, float o2v, int o2i) {
    if (keybetter(o1v, o1i, v1, i1)) {
        if (keybetter(v1, i1, o2v, o2i)) { v2 = v1; i2 = i1; }
        else                             { v2 = o2v; i2 = o2i; }
        v1 = o1v; i1 = o1i;
    } else if (keybetter(o1v, o1i, v2, i2)) { v2 = o1v; i2 = o1i; }
}

// ---------------- kernel 1: fused detect + norms + fp16 convert ----------------
__global__ void k_prep(const float* __restrict__ emb, const float* __restrict__ clot,
                       const void* __restrict__ lab) {
    int r = blockIdx.x, t = threadIdx.x;
    int lane = t & 31, w = t >> 5;
    if (r == 0 && t == 0) {
        const unsigned* p = (const unsigned*)lab;
        int is64 = 1;
        for (int i = 0; i < 64; i++) if (p[2 * i + 1] != 0u) { is64 = 0; break; }
        g_lab64 = is64;
    }
    float4 v = ((const float4*)(emb + (size_t)r * DIM))[t];
    float s = v.x * v.x + v.y * v.y + v.z * v.z + v.w * v.w;
    size_t o = (size_t)r * DIM + t * 4;
    *(__half2*)(g_hi + o)     = __half2(__float2half(v.x), __float2half(v.y));
    *(__half2*)(g_hi + o + 2) = __half2(__float2half(v.z), __float2half(v.w));
    float c = 0.f;
    if (t < DIM2 / 4) {
        float4 wv = ((const float4*)(clot + (size_t)r * DIM2))[t];
        c = wv.x * wv.x + wv.y * wv.y + wv.z * wv.z + wv.w * wv.w;
    }
    #pragma unroll
    for (int o2 = 16; o2 > 0; o2 >>= 1) {
        s += __shfl_xor_sync(0xffffffffu, s, o2);
        c += __shfl_xor_sync(0xffffffffu, c, o2);
    }
    __shared__ float se[8], sc[8];
    if (lane == 0) { se[w] = s; sc[w] = c; }
    __syncthreads();
    if (t == 0) {
        float ss = 0.f, cc = 0.f;
        #pragma unroll
        for (int i = 0; i < 8; i++) { ss += se[i]; cc += sc[i]; }
        g_sq[r] = ss; g_nrm[r] = sqrtf(cc);
    }
}

// ---------------- kernel 2: fp16 single-pass HMMA GEMM, K=64 stages ----------------
// ring of 3 x 32KB; 16 barrier rounds/tile; d^2-domain selection; diagonal tiles last.
__global__ __launch_bounds__(256, 2) void k_dist_mma(const void* __restrict__ lab) {
    extern __shared__ char smem[];
    const uint32_t sb = smem_u32(smem);
    const int tid = threadIdx.x;
    const int lane = tid & 31, wid = tid >> 5;
    const int wm = wid >> 2, wn = wid & 3;
    const int lab64 = g_lab64;

    // tile id -> (rb, cb): ids [0,2016) strictly-upper, [2016,2080) diagonal (run last)
    int rb, cb;
    if (blockIdx.x < NOFFD) {
        int u = blockIdx.x; rb = 0;
        while (u >= 63 - rb) { u -= 63 - rb; rb++; }
        cb = rb + 1 + u;
    } else {
        rb = cb = blockIdx.x - NOFFD;
    }
    const int r0 = rb * BM, c0 = cb * BN;

    // ---- per-thread cp.async descriptors (8 x 16B per stage: 4 A + 4 B) ----
    const char* srcp[8];
    uint32_t dsto[8];
    #pragma unroll
    for (int v = 0; v < 4; v++) {          // A: 1024 ops (128 rows x 8 segs)
        int i = tid + v * 256;
        int row = i >> 3, seg = i & 7;
        srcp[v] = (const char*)(g_hi + (size_t)(r0 + row) * DIM + seg * 8);
        dsto[v] = sw128((uint32_t)row * 128u + (uint32_t)seg * 16u);
    }
    #pragma unroll
    for (int v = 4; v < 8; v++) {          // B: 1024 ops
        int j = tid + (v - 4) * 256;
        int row = j >> 3, seg = j & 7;
        srcp[v] = (const char*)(g_hi + (size_t)(c0 + row) * DIM + seg * 8);
        dsto[v] = B_OFF + sw128((uint32_t)row * 128u + (uint32_t)seg * 16u);
    }

    // ---- ldmatrix pre-offsets + row-dependent swizzle masks (128B rows) ----
    uint32_t preA[4], mskA[4], preB[2], mskB[2];
    {
        int rA = wm * 64 + (lane & 15);
        int sA = lane >> 4;
        #pragma unroll
        for (int mt = 0; mt < 4; mt++) {
            uint32_t p = (uint32_t)(rA + mt * 16) * 128u + (uint32_t)sA * 16u;
            mskA[mt] = (p >> 3) & 0x70u;
            preA[mt] = p;
        }
        int rB = wn * 32 + ((lane >> 4) << 3) + (lane & 7);
        int sB = (lane >> 3) & 1;
        #pragma unroll
        for (int np = 0; np < 2; np++) {
            uint32_t p = (uint32_t)(rB + np * 16) * 128u + (uint32_t)sB * 16u;
            mskB[np] = (p >> 3) & 0x70u;
            preB[np] = p;
        }
    }

    float acc[4][4][4];
    #pragma unroll
    for (int a = 0; a < 4; a++)
        #pragma unroll
        for (int b = 0; b < 4; b++)
            #pragma unroll
            for (int c = 0; c < 4; c++) acc[a][b][c] = 0.f;

    // ---- prologue: fill 2 stages (bufs 0,1) ----
    #pragma unroll
    for (int p = 0; p < 2; p++) {
        uint32_t db = sb + (uint32_t)p * STAGE_BYTES;
        #pragma unroll
        for (int v = 0; v < 8; v++) cpasync16(db + dsto[v], srcp[v] + (size_t)p * 128);
        CP_COMMIT();
    }

    // ---- main loop: 16 K-stages of 64; ring of 3 ----
    int buf = 0;          // buffer holding stage s
    int pbuf = 2;         // buffer receiving stage s+2
    for (int s = 0; s < NSTAGES_K; s++) {
        CP_WAIT1();
        __syncthreads();
        {
            int sn = s + 2;
            if (sn < NSTAGES_K) {
                uint32_t db = sb + (uint32_t)pbuf * STAGE_BYTES;
                #pragma unroll
                for (int v = 0; v < 8; v++) cpasync16(db + dsto[v], srcp[v] + (size_t)sn * 128);
            }
            CP_COMMIT();   // may be empty; keeps wait_group accounting uniform
        }
        const uint32_t base = sb + (uint32_t)buf * STAGE_BYTES;
        const uint32_t baseB = base + B_OFF;
        if (++buf == NSTG) buf = 0;
        if (++pbuf == NSTG) pbuf = 0;

        #pragma unroll
        for (int kc = 0; kc < 4; kc++) {
            const uint32_t kd = (uint32_t)kc * 32u;
            uint32_t BH[2][4];
            #pragma unroll
            for (int np = 0; np < 2; np++)
                LDM4(BH[np], baseB + ((preB[np] + kd) ^ mskB[np]));
            uint32_t AH[4][4];
            #pragma unroll
            for (int mt = 0; mt < 4; mt++)
                LDM4(AH[mt], base + ((preA[mt] + kd) ^ mskA[mt]));
            #pragma unroll
            for (int mt = 0; mt < 4; mt++)
                #pragma unroll
                for (int nt = 0; nt < 4; nt++)
                    MMA16816(acc[mt][nt], AH[mt], BH[nt >> 1][(nt & 1) * 2], BH[nt >> 1][(nt & 1) * 2 + 1]);
        }
    }
    CP_WAIT0();
    __syncthreads();   // ring dead; smem reused below

    const int tg = lane & 3, g = lane >> 2;
    float sqj[8]; int labj[8];
    #pragma unroll
    for (int ln = 0; ln < 8; ln++) {
        int cc = c0 + wn * 32 + (ln >> 1) * 8 + tg * 2 + (ln & 1);
        sqj[ln] = g_sq[cc];
        labj[ln] = getlab(lab, cc, lab64);
    }
    float sqi[8]; int labi[8];
    #pragma unroll
    for (int lm = 0; lm < 8; lm++) {
        int m = r0 + wm * 64 + (lm >> 1) * 16 + g + (lm & 1) * 8;
        sqi[lm] = g_sq[m];
        labi[lm] = getlab(lab, m, lab64);
    }

    // smem overlays
    float* sv1 = (float*)smem;              // [128][4]
    float* sv2 = (float*)(smem + 2048);
    float* smn = (float*)(smem + 4096);
    int*   si1 = (int*)(smem + 6144);
    int*   si2 = (int*)(smem + 8192);
    float* cv1 = (float*)(smem + 16384);    // [128][2]
    float* cv2 = (float*)(smem + 17408);
    float* cmn = (float*)(smem + 18432);
    int*   ci1 = (int*)(smem + 19456);
    int*   ci2 = (int*)(smem + 20480);

    // ======== row stats (d^2 domain; d^2 stored back into acc for col pass) ========
    {
        float b1v[8], b2v[8], mnv[8]; int b1i[8], b2i[8];
        #pragma unroll
        for (int lm = 0; lm < 8; lm++) {
            float v1 = -INFINITY, v2 = -INFINITY, mn = INFINITY;
            int i1 = 0x7fffffff, i2 = 0x7fffffff;
            #pragma unroll
            for (int ln = 0; ln < 8; ln++) {
                int col = c0 + wn * 32 + (ln >> 1) * 8 + tg * 2 + (ln & 1);
                float& ar = acc[lm >> 1][ln >> 1][(lm & 1) * 2 + (ln & 1)];
                float d2 = fmaf(-2.0f, ar, sqi[lm] + sqj[ln]);
                ar = d2;
                bool same = (labi[lm] == labj[ln]);
                float pv = same ? d2 : d2 - BIGF;
                float nv = same ? d2 + BIGF : d2;
                mn = fminf(mn, nv);
                if (keybetter(pv, col, v1, i1)) { v2 = v1; i2 = i1; v1 = pv; i1 = col; }
                else if (keybetter(pv, col, v2, i2)) { v2 = pv; i2 = col; }
            }
            b1v[lm] = v1; b1i[lm] = i1; b2v[lm] = v2; b2i[lm] = i2; mnv[lm] = mn;
        }
        #pragma unroll
        for (int lm = 0; lm < 8; lm++) {
            #pragma unroll
            for (int off = 1; off <= 2; off <<= 1) {
                float o1v = __shfl_xor_sync(0xffffffffu, b1v[lm], off);
                int   o1i = __shfl_xor_sync(0xffffffffu, b1i[lm], off);
                float o2v = __shfl_xor_sync(0xffffffffu, b2v[lm], off);
                int   o2i = __shfl_xor_sync(0xffffffffu, b2i[lm], off);
                float omn = __shfl_xor_sync(0xffffffffu, mnv[lm], off);
                mnv[lm] = fminf(mnv[lm], omn);
                merge2(b1v[lm], b1i[lm], b2v[lm], b2i[lm], o1v, o1i, o2v, o2i);
            }
        }
        if (tg == 0) {
            #pragma unroll
            for (int lm = 0; lm < 8; lm++) {
                int rl = wm * 64 + (lm >> 1) * 16 + g + (lm & 1) * 8;
                sv1[rl * 4 + wn] = b1v[lm]; si1[rl * 4 + wn] = b1i[lm];
                sv2[rl * 4 + wn] = b2v[lm]; si2[rl * 4 + wn] = b2i[lm];
                smn[rl * 4 + wn] = mnv[lm];
            }
        }
    }

    // ======== col stats (transposed harvest; skip on diagonal) ========
    if (rb != cb) {
        float b1v[8], b2v[8], mnv[8]; int b1i[8], b2i[8];
        #pragma unroll
        for (int ln = 0; ln < 8; ln++) {
            float v1 = -INFINITY, v2 = -INFINITY, mn = INFINITY;
            int i1 = 0x7fffffff, i2 = 0x7fffffff;
            #pragma unroll
            for (int lm = 0; lm < 8; lm++) {
                int rowidx = r0 + wm * 64 + (lm >> 1) * 16 + g + (lm & 1) * 8;
                float d2 = acc[lm >> 1][ln >> 1][(lm & 1) * 2 + (ln & 1)];
                bool same = (labi[lm] == labj[ln]);
                float pv = same ? d2 : d2 - BIGF;
                float nv = same ? d2 + BIGF : d2;
                mn = fminf(mn, nv);
                if (keybetter(pv, rowidx, v1, i1)) { v2 = v1; i2 = i1; v1 = pv; i1 = rowidx; }
                else if (keybetter(pv, rowidx, v2, i2)) { v2 = pv; i2 = rowidx; }
            }
            b1v[ln] = v1; b1i[ln] = i1; b2v[ln] = v2; b2i[ln] = i2; mnv[ln] = mn;
        }
        #pragma unroll
        for (int ln = 0; ln < 8; ln++) {
            #pragma unroll
            for (int off = 4; off <= 16; off <<= 1) {
                float o1v = __shfl_xor_sync(0xffffffffu, b1v[ln], off);
                int   o1i = __shfl_xor_sync(0xffffffffu, b1i[ln], off);
                float o2v = __shfl_xor_sync(0xffffffffu, b2v[ln], off);
                int   o2i = __shfl_xor_sync(0xffffffffu, b2i[ln], off);
                float omn = __shfl_xor_sync(0xffffffffu, mnv[ln], off);
                mnv[ln] = fminf(mnv[ln], omn);
                merge2(b1v[ln], b1i[ln], b2v[ln], b2i[ln], o1v, o1i, o2v, o2i);
            }
        }
        if (g == 0) {
            #pragma unroll
            for (int ln = 0; ln < 8; ln++) {
                int cl = wn * 32 + (ln >> 1) * 8 + tg * 2 + (ln & 1);
                cv1[cl * 2 + wm] = b1v[ln]; ci1[cl * 2 + wm] = b1i[ln];
                cv2[cl * 2 + wm] = b2v[ln]; ci2[cl * 2 + wm] = b2i[ln];
                cmn[cl * 2 + wm] = mnv[ln];
            }
        }
    }
    __syncthreads();

    // final merges + global writes: threads 0-127 row-merge, 128-255 col-merge (parallel)
    if (tid < 128) {
        float v1 = -INFINITY, v2 = -INFINITY, mn = INFINITY;
        int i1 = 0x7fffffff, i2 = 0x7fffffff;
        #pragma unroll
        for (int w = 0; w < 4; w++) {
            mn = fminf(mn, smn[tid * 4 + w]);
            merge2(v1, i1, v2, i2, sv1[tid * 4 + w], si1[tid * 4 + w], sv2[tid * 4 + w], si2[tid * 4 + w]);
        }
        int r = r0 + tid;
        g_p1v[cb][r] = v1; g_p1i[cb][r] = i1;
        g_p2v[cb][r] = v2; g_p2i[cb][r] = i2;
        g_pmn[cb][r] = mn;
    } else if (rb != cb) {
        int t2 = tid - 128;
        float v1 = -INFINITY, v2 = -INFINITY, mn = INFINITY;
        int i1 = 0x7fffffff, i2 = 0x7fffffff;
        #pragma unroll
        for (int w = 0; w < 2; w++) {
            mn = fminf(mn, cmn[t2 * 2 + w]);
            merge2(v1, i1, v2, i2, cv1[t2 * 2 + w], ci1[t2 * 2 + w], cv2[t2 * 2 + w], ci2[t2 * 2 + w]);
        }
        int r = c0 + t2;
        g_p1v[rb][r] = v1; g_p1i[rb][r] = i1;
        g_p2v[rb][r] = v2; g_p2i[rb][r] = i2;
        g_pmn[rb][r] = mn;
    }
}

// ---------------- kernel 3: fused warp-per-row merge + d^2->dist + cos dots ----------------
__global__ void k_merge_alpha(const float* __restrict__ clot) {
    int t = threadIdx.x;
    int r = blockIdx.x * 8 + (t >> 5);
    int l = t & 31;
    float b1v = g_p1v[l][r]; int b1i = g_p1i[l][r];
    float b2v = g_p2v[l][r]; int b2i = g_p2i[l][r];
    float mn  = g_pmn[l][r];
    int c2 = l + 32;
    mn = fminf(mn, g_pmn[c2][r]);
    merge2(b1v, b1i, b2v, b2i, g_p1v[c2][r], g_p1i[c2][r], g_p2v[c2][r], g_p2i[c2][r]);
    #pragma unroll
    for (int off = 16; off > 0; off >>= 1) {
        float o1v = __shfl_xor_sync(0xffffffffu, b1v, off);
        int   o1i = __shfl_xor_sync(0xffffffffu, b1i, off);
        float o2v = __shfl_xor_sync(0xffffffffu, b2v, off);
        int   o2i = __shfl_xor_sync(0xffffffffu, b2i, off);
        float omn = __shfl_xor_sync(0xffffffffu, mn,  off);
        mn = fminf(mn, omn);
        merge2(b1v, b1i, b2v, b2i, o1v, o1i, o2v, o2i);
    }
    int j1 = b1i, j2 = b2i;
    const float* cr = clot + (size_t)r * DIM2;
    const float* ca = clot + (size_t)j1 * DIM2;
    const float* cb = clot + (size_t)j2 * DIM2;
    float d1 = 0.f, d2 = 0.f;
    #pragma unroll 4
    for (int k = l; k < DIM2; k += 32) {
        float c = cr[k];
        d1 = fmaf(c, ca[k], d1);
        d2 = fmaf(c, cb[k], d2);
    }
    #pragma unroll
    for (int o = 16; o > 0; o >>= 1) {
        d1 += __shfl_xor_sync(0xffffffffu, d1, o);
        d2 += __shfl_xor_sync(0xffffffffu, d2, o);
    }
    if (l == 0) {
        float ap1 = (b1v < -1e6f) ? (sqrtf(fmaxf(b1v + BIGF, 1e-12f)) - BIGF)
                                  : sqrtf(fmaxf(b1v, 1e-12f));
        float ap2 = (b2v < -1e6f) ? (sqrtf(fmaxf(b2v + BIGF, 1e-12f)) - BIGF)
                                  : sqrtf(fmaxf(b2v, 1e-12f));
        float an  = (mn > 1e6f) ? (sqrtf(fmaxf(mn - BIGF, 1e-12f)) + BIGF)
                                : sqrtf(fmaxf(mn, 1e-12f));
        g_ap1[r] = ap1; g_ap2[r] = ap2; g_an[r] = an;
        g_a1[r] = d1 / (g_nrm[r] * g_nrm[j1]);
        g_a2[r] = d2 / (g_nrm[r] * g_nrm[j2]);
    }
}

// ---------------- kernel 4a: per-block loss partials ----------------
__global__ void k_final_part() {
    int t = threadIdx.x;
    int r = blockIdx.x * 256 + t;
    float ap1 = g_ap1[r], ap2 = g_ap2[r], an = g_an[r];
    float a1 = g_a1[r], a2 = g_a2[r];
    float y  = (a1 < a2) ? -1.f : 1.f;
    float ym = (a1 == a2) ? 0.f : 1.f;
    float x1 = ap2 * ym;
    float x2 = ap1 * ym + MARGINF * (a1 - a2 - y);
    float t11 = fmaxf(0.f, -y * (x1 - x2) + MARGINF);
    float ap1m = ap1 + MARGINF * (a1 - 1.f);
    float t13 = fmaxf(0.f, -(an - ap1m) + MARGINF);
    float tp = (an > ap1m) ? 1.f : 0.f;
    #pragma unroll
    for (int o = 16; o > 0; o >>= 1) {
        t11 += __shfl_xor_sync(0xffffffffu, t11, o);
        t13 += __shfl_xor_sync(0xffffffffu, t13, o);
        tp  += __shfl_xor_sync(0xffffffffu, tp,  o);
    }
    __shared__ float s1[8], s2[8], s3[8];
    int w = t >> 5, l = t & 31;
    if (l == 0) { s1[w] = t11; s2[w] = t13; s3[w] = tp; }
    __syncthreads();
    if (t == 0) {
        float a = 0.f, b = 0.f, c = 0.f;
        #pragma unroll
        for (int i = 0; i < 8; i++) { a += s1[i]; b += s2[i]; c += s3[i]; }
        g_fin[blockIdx.x][0] = a;
        g_fin[blockIdx.x][1] = b;
        g_fin[blockIdx.x][2] = c;
    }
}

// ---------------- kernel 4b: combine 32 partials ----------------
__global__ void k_final2(float* __restrict__ out) {
    int t = threadIdx.x;  // 32 threads
    float a = g_fin[t][0], b = g_fin[t][1], c = g_fin[t][2];
    #pragma unroll
    for (int o = 16; o > 0; o >>= 1) {
        a += __shfl_xor_sync(0xffffffffu, a, o);
        b += __shfl_xor_sync(0xffffffffu, b, o);
        c += __shfl_xor_sync(0xffffffffu, c, o);
    }
    if (t == 0) {
        out[0] = 0.1f * (a / (float)NROW) + (b / (float)NROW);
        out[1] = c / (float)NROW;
    }
}

// ---------------- launch ----------------
extern "C" void kernel_launch(void* const* d_in, const int* in_sizes, int n_in,
                              void* d_out, int out_size) {
    const float* emb  = (const float*)d_in[0];
    const void*  lab  = d_in[1];
    const float* clot = (const float*)d_in[2];
    float* out = (float*)d_out;

    cudaFuncSetAttribute(k_dist_mma, cudaFuncAttributeMaxDynamicSharedMemorySize, SMEM_TOTAL);

    k_prep<<<NROW, 256>>>(emb, clot, lab);
    k_dist_mma<<<NTILE, 256, SMEM_TOTAL>>>(lab);
    k_merge_alpha<<<NROW / 8, 256>>>(clot);
    k_final_part<<<32, 256>>>();
    k_final2<<<1, 32>>>(out);
}

// round 15
// speedup vs baseline: 1.2543x; 1.0046x over previous
#include <cuda_runtime.h>
#include <cuda_fp16.h>
#include <math.h>
#include <stdint.h>

#define NROW 8192
#define DIM 1024
#define DIM2 512
#define BM 128
#define BN 128
#define NCT (NROW / BN)            // 64 partial slots
#define NTILE 2080                 // 64*65/2 upper-triangle tiles
#define NOFFD 2016                 // strictly-upper tiles
#define BIGF 9999999.0f
#define MARGINF 0.3f

#define STAGE_BYTES 32768          // A (128x128B) + B (128x128B), K=64 halfs
#define B_OFF 16384
#define NSTG 3
#define SMEM_TOTAL (NSTG * STAGE_BYTES)   // 96 KB
#define NSTAGES_K 16               // 1024 / 64

// ---------------- device scratch ----------------
__device__ int   g_lab64;
__device__ float g_sq[NROW];
__device__ float g_nrm[NROW];
__device__ __half g_hi[(size_t)NROW * DIM];
__device__ float g_p1v[NCT][NROW];
__device__ float g_p2v[NCT][NROW];
__device__ int   g_p1i[NCT][NROW];
__device__ int   g_p2i[NCT][NROW];
__device__ float g_pmn[NCT][NROW];
__device__ float g_ap1[NROW], g_ap2[NROW], g_an[NROW];
__device__ float g_a1[NROW], g_a2[NROW];
__device__ float g_fin[32][3];

// ---------------- helpers ----------------
__device__ __forceinline__ uint32_t smem_u32(const void* p) {
    uint32_t a;
    asm("{ .reg .u64 t; cvta.to.shared.u64 t, %1; cvt.u32.u64 %0, t; }" : "=r"(a) : "l"(p));
    return a;
}
__device__ __forceinline__ void cpasync16(uint32_t dst, const void* src) {
    asm volatile("cp.async.cg.shared.global [%0], [%1], 16;" :: "r"(dst), "l"(src));
}
#define CP_COMMIT() asm volatile("cp.async.commit_group;" ::: "memory")
#define CP_WAIT1()  asm volatile("cp.async.wait_group 1;" ::: "memory")
#define CP_WAIT0()  asm volatile("cp.async.wait_group 0;" ::: "memory")

#define LDM4(r, addr) \
    asm volatile("ldmatrix.sync.aligned.m8n8.x4.shared.b16 {%0,%1,%2,%3}, [%4];" \
        : "=r"((r)[0]), "=r"((r)[1]), "=r"((r)[2]), "=r"((r)[3]) : "r"(addr))

#define MMA16816(c, a, b0_, b1_) \
    asm volatile("mma.sync.aligned.m16n8k16.row.col.f32.f16.f16.f32 " \
        "{%0,%1,%2,%3}, {%4,%5,%6,%7}, {%8,%9}, {%0,%1,%2,%3};" \
        : "+f"((c)[0]), "+f"((c)[1]), "+f"((c)[2]), "+f"((c)[3]) \
        : "r"((a)[0]), "r"((a)[1]), "r"((a)[2]), "r"((a)[3]), "r"(b0_), "r"(b1_))

__device__ __forceinline__ int getlab(const void* lab, int i, int is64) {
    if (is64) return (int)((const long long*)lab)[i];
    return ((const int*)lab)[i];
}
__device__ __forceinline__ bool keybetter(float av, int ai, float bv, int bi) {
    return (av > bv) || (av == bv && ai < bi);
}
__device__ __forceinline__ uint32_t sw128(uint32_t off) { return off ^ ((off >> 3) & 0x70u); }

__device__ __forceinline__ void merge2(float& v1, int& i1, float& v2, int& i2,
                                       float o1v, int o1i, float o2v, int o2i) {
    if (keybetter(o1v, o1i, v1, i1)) {
        if (keybetter(v1, i1, o2v, o2i)) { v2 = v1; i2 = i1; }
        else                             { v2 = o2v; i2 = o2i; }
        v1 = o1v; i1 = o1i;
    } else if (keybetter(o1v, o1i, v2, i2)) { v2 = o1v; i2 = o1i; }
}

// ---------------- kernel 1: fused detect + norms + fp16 convert ----------------
__global__ void k_prep(const float* __restrict__ emb, const float* __restrict__ clot,
                       const void* __restrict__ lab) {
    int r = blockIdx.x, t = threadIdx.x;
    int lane = t & 31, w = t >> 5;
    if (r == 0 && t == 0) {
        const unsigned* p = (const unsigned*)lab;
        int is64 = 1;
        for (int i = 0; i < 64; i++) if (p[2 * i + 1] != 0u) { is64 = 0; break; }
        g_lab64 = is64;
    }
    float4 v = ((const float4*)(emb + (size_t)r * DIM))[t];
    float s = v.x * v.x + v.y * v.y + v.z * v.z + v.w * v.w;
    size_t o = (size_t)r * DIM + t * 4;
    *(__half2*)(g_hi + o)     = __half2(__float2half(v.x), __float2half(v.y));
    *(__half2*)(g_hi + o + 2) = __half2(__float2half(v.z), __float2half(v.w));
    float c = 0.f;
    if (t < DIM2 / 4) {
        float4 wv = ((const float4*)(clot + (size_t)r * DIM2))[t];
        c = wv.x * wv.x + wv.y * wv.y + wv.z * wv.z + wv.w * wv.w;
    }
    #pragma unroll
    for (int o2 = 16; o2 > 0; o2 >>= 1) {
        s += __shfl_xor_sync(0xffffffffu, s, o2);
        c += __shfl_xor_sync(0xffffffffu, c, o2);
    }
    __shared__ float se[8], sc[8];
    if (lane == 0) { se[w] = s; sc[w] = c; }
    __syncthreads();
    if (t == 0) {
        float ss = 0.f, cc = 0.f;
        #pragma unroll
        for (int i = 0; i < 8; i++) { ss += se[i]; cc += sc[i]; }
        g_sq[r] = ss; g_nrm[r] = sqrtf(cc);
    }
}

// ---------------- kernel 2: fp16 single-pass HMMA GEMM, K=64 stages ----------------
// ring of 3 x 32KB; per-warp kc rotation to desync LDSM bursts; diagonal tiles last.
__global__ __launch_bounds__(256, 2) void k_dist_mma(const void* __restrict__ lab) {
    extern __shared__ char smem[];
    const uint32_t sb = smem_u32(smem);
    const int tid = threadIdx.x;
    const int lane = tid & 31, wid = tid >> 5;
    const int wm = wid >> 2, wn = wid & 3;
    const int lab64 = g_lab64;

    // tile id -> (rb, cb): ids [0,2016) strictly-upper, [2016,2080) diagonal (run last)
    int rb, cb;
    if (blockIdx.x < NOFFD) {
        int u = blockIdx.x; rb = 0;
        while (u >= 63 - rb) { u -= 63 - rb; rb++; }
        cb = rb + 1 + u;
    } else {
        rb = cb = blockIdx.x - NOFFD;
    }
    const int r0 = rb * BM, c0 = cb * BN;

    // ---- per-thread cp.async descriptors (8 x 16B per stage: 4 A + 4 B) ----
    const char* srcp[8];
    uint32_t dsto[8];
    #pragma unroll
    for (int v = 0; v < 4; v++) {          // A: 1024 ops (128 rows x 8 segs)
        int i = tid + v * 256;
        int row = i >> 3, seg = i & 7;
        srcp[v] = (const char*)(g_hi + (size_t)(r0 + row) * DIM + seg * 8);
        dsto[v] = sw128((uint32_t)row * 128u + (uint32_t)seg * 16u);
    }
    #pragma unroll
    for (int v = 4; v < 8; v++) {          // B: 1024 ops
        int j = tid + (v - 4) * 256;
        int row = j >> 3, seg = j & 7;
        srcp[v] = (const char*)(g_hi + (size_t)(c0 + row) * DIM + seg * 8);
        dsto[v] = B_OFF + sw128((uint32_t)row * 128u + (uint32_t)seg * 16u);
    }

    // ---- ldmatrix pre-offsets + row-dependent swizzle masks (128B rows) ----
    uint32_t preA[4], mskA[4], preB[2], mskB[2];
    {
        int rA = wm * 64 + (lane & 15);
        int sA = lane >> 4;
        #pragma unroll
        for (int mt = 0; mt < 4; mt++) {
            uint32_t p = (uint32_t)(rA + mt * 16) * 128u + (uint32_t)sA * 16u;
            mskA[mt] = (p >> 3) & 0x70u;
            preA[mt] = p;
        }
        int rB = wn * 32 + ((lane >> 4) << 3) + (lane & 7);
        int sB = (lane >> 3) & 1;
        #pragma unroll
        for (int np = 0; np < 2; np++) {
            uint32_t p = (uint32_t)(rB + np * 16) * 128u + (uint32_t)sB * 16u;
            mskB[np] = (p >> 3) & 0x70u;
            preB[np] = p;
        }
    }

    float acc[4][4][4];
    #pragma unroll
    for (int a = 0; a < 4; a++)
        #pragma unroll
        for (int b = 0; b < 4; b++)
            #pragma unroll
            for (int c = 0; c < 4; c++) acc[a][b][c] = 0.f;

    // ---- prologue: fill 2 stages (bufs 0,1) ----
    #pragma unroll
    for (int p = 0; p < 2; p++) {
        uint32_t db = sb + (uint32_t)p * STAGE_BYTES;
        #pragma unroll
        for (int v = 0; v < 8; v++) cpasync16(db + dsto[v], srcp[v] + (size_t)p * 128);
        CP_COMMIT();
    }

    // ---- main loop: 16 K-stages of 64; ring of 3; per-warp kc rotation ----
    int buf = 0;          // buffer holding stage s
    int pbuf = 2;         // buffer receiving stage s+2
    const int krot = wid & 3;
    for (int s = 0; s < NSTAGES_K; s++) {
        CP_WAIT1();
        __syncthreads();
        {
            int sn = s + 2;
            if (sn < NSTAGES_K) {
                uint32_t db = sb + (uint32_t)pbuf * STAGE_BYTES;
                #pragma unroll
                for (int v = 0; v < 8; v++) cpasync16(db + dsto[v], srcp[v] + (size_t)sn * 128);
            }
            CP_COMMIT();   // may be empty; keeps wait_group accounting uniform
        }
        const uint32_t base = sb + (uint32_t)buf * STAGE_BYTES;
        const uint32_t baseB = base + B_OFF;
        if (++buf == NSTG) buf = 0;
        if (++pbuf == NSTG) pbuf = 0;

        #pragma unroll
        for (int kci = 0; kci < 4; kci++) {
            const int kc = (kci + krot) & 3;
            const uint32_t kd = (uint32_t)kc * 32u;
            uint32_t BH[2][4];
            #pragma unroll
            for (int np = 0; np < 2; np++)
                LDM4(BH[np], baseB + ((preB[np] + kd) ^ mskB[np]));
            uint32_t AH[4][4];
            #pragma unroll
            for (int mt = 0; mt < 4; mt++)
                LDM4(AH[mt], base + ((preA[mt] + kd) ^ mskA[mt]));
            #pragma unroll
            for (int mt = 0; mt < 4; mt++)
                #pragma unroll
                for (int nt = 0; nt < 4; nt++)
                    MMA16816(acc[mt][nt], AH[mt], BH[nt >> 1][(nt & 1) * 2], BH[nt >> 1][(nt & 1) * 2 + 1]);
        }
    }

    // ---- epilogue global loads issued before the drain (overlap) ----
    const int tg = lane & 3, g = lane >> 2;
    float sqj[8]; int labj[8];
    #pragma unroll
    for (int ln = 0; ln < 8; ln++) {
        int cc = c0 + wn * 32 + (ln >> 1) * 8 + tg * 2 + (ln & 1);
        sqj[ln] = g_sq[cc];
        labj[ln] = getlab(lab, cc, lab64);
    }
    float sqi[8]; int labi[8];
    #pragma unroll
    for (int lm = 0; lm < 8; lm++) {
        int m = r0 + wm * 64 + (lm >> 1) * 16 + g + (lm & 1) * 8;
        sqi[lm] = g_sq[m];
        labi[lm] = getlab(lab, m, lab64);
    }

    CP_WAIT0();
    __syncthreads();   // ring dead; smem reused below

    // smem overlays
    float* sv1 = (float*)smem;              // [128][4]
    float* sv2 = (float*)(smem + 2048);
    float* smn = (float*)(smem + 4096);
    int*   si1 = (int*)(smem + 6144);
    int*   si2 = (int*)(smem + 8192);
    float* cv1 = (float*)(smem + 16384);    // [128][2]
    float* cv2 = (float*)(smem + 17408);
    float* cmn = (float*)(smem + 18432);
    int*   ci1 = (int*)(smem + 19456);
    int*   ci2 = (int*)(smem + 20480);

    // ======== row stats (d^2 domain; d^2 stored back into acc for col pass) ========
    {
        float b1v[8], b2v[8], mnv[8]; int b1i[8], b2i[8];
        #pragma unroll
        for (int lm = 0; lm < 8; lm++) {
            float v1 = -INFINITY, v2 = -INFINITY, mn = INFINITY;
            int i1 = 0x7fffffff, i2 = 0x7fffffff;
            #pragma unroll
            for (int ln = 0; ln < 8; ln++) {
                int col = c0 + wn * 32 + (ln >> 1) * 8 + tg * 2 + (ln & 1);
                float& ar = acc[lm >> 1][ln >> 1][(lm & 1) * 2 + (ln & 1)];
                float d2 = fmaf(-2.0f, ar, sqi[lm] + sqj[ln]);
                ar = d2;
                bool same = (labi[lm] == labj[ln]);
                float pv = same ? d2 : d2 - BIGF;
                float nv = same ? d2 + BIGF : d2;
                mn = fminf(mn, nv);
                if (keybetter(pv, col, v1, i1)) { v2 = v1; i2 = i1; v1 = pv; i1 = col; }
                else if (keybetter(pv, col, v2, i2)) { v2 = pv; i2 = col; }
            }
            b1v[lm] = v1; b1i[lm] = i1; b2v[lm] = v2; b2i[lm] = i2; mnv[lm] = mn;
        }
        #pragma unroll
        for (int lm = 0; lm < 8; lm++) {
            #pragma unroll
            for (int off = 1; off <= 2; off <<= 1) {
                float o1v = __shfl_xor_sync(0xffffffffu, b1v[lm], off);
                int   o1i = __shfl_xor_sync(0xffffffffu, b1i[lm], off);
                float o2v = __shfl_xor_sync(0xffffffffu, b2v[lm], off);
                int   o2i = __shfl_xor_sync(0xffffffffu, b2i[lm], off);
                float omn = __shfl_xor_sync(0xffffffffu, mnv[lm], off);
                mnv[lm] = fminf(mnv[lm], omn);
                merge2(b1v[lm], b1i[lm], b2v[lm], b2i[lm], o1v, o1i, o2v, o2i);
            }
        }
        if (tg == 0) {
            #pragma unroll
            for (int lm = 0; lm < 8; lm++) {
                int rl = wm * 64 + (lm >> 1) * 16 + g + (lm & 1) * 8;
                sv1[rl * 4 + wn] = b1v[lm]; si1[rl * 4 + wn] = b1i[lm];
                sv2[rl * 4 + wn] = b2v[lm]; si2[rl * 4 + wn] = b2i[lm];
                smn[rl * 4 + wn] = mnv[lm];
            }
        }
    }

    // ======== col stats (transposed harvest; skip on diagonal) ========
    if (rb != cb) {
        float b1v[8], b2v[8], mnv[8]; int b1i[8], b2i[8];
        #pragma unroll
        for (int ln = 0; ln < 8; ln++) {
            float v1 = -INFINITY, v2 = -INFINITY, mn = INFINITY;
            int i1 = 0x7fffffff, i2 = 0x7fffffff;
            #pragma unroll
            for (int lm = 0; lm < 8; lm++) {
                int rowidx = r0 + wm * 64 + (lm >> 1) * 16 + g + (lm & 1) * 8;
                float d2 = acc[lm >> 1][ln >> 1][(lm & 1) * 2 + (ln & 1)];
                bool same = (labi[lm] == labj[ln]);
                float pv = same ? d2 : d2 - BIGF;
                float nv = same ? d2 + BIGF : d2;
                mn = fminf(mn, nv);
                if (keybetter(pv, rowidx, v1, i1)) { v2 = v1; i2 = i1; v1 = pv; i1 = rowidx; }
                else if (keybetter(pv, rowidx, v2, i2)) { v2 = pv; i2 = rowidx; }
            }
            b1v[ln] = v1; b1i[ln] = i1; b2v[ln] = v2; b2i[ln] = i2; mnv[ln] = mn;
        }
        #pragma unroll
        for (int ln = 0; ln < 8; ln++) {
            #pragma unroll
            for (int off = 4; off <= 16; off <<= 1) {
                float o1v = __shfl_xor_sync(0xffffffffu, b1v[ln], off);
                int   o1i = __shfl_xor_sync(0xffffffffu, b1i[ln], off);
                float o2v = __shfl_xor_sync(0xffffffffu, b2v[ln], off);
                int   o2i = __shfl_xor_sync(0xffffffffu, b2i[ln], off);
                float omn = __shfl_xor_sync(0xffffffffu, mnv[ln], off);
                mnv[ln] = fminf(mnv[ln], omn);
                merge2(b1v[ln], b1i[ln], b2v[ln], b2i[ln], o1v, o1i, o2v, o2i);
            }
        }
        if (g == 0) {
            #pragma unroll
            for (int ln = 0; ln < 8; ln++) {
                int cl = wn * 32 + (ln >> 1) * 8 + tg * 2 + (ln & 1);
                cv1[cl * 2 + wm] = b1v[ln]; ci1[cl * 2 + wm] = b1i[ln];
                cv2[cl * 2 + wm] = b2v[ln]; ci2[cl * 2 + wm] = b2i[ln];
                cmn[cl * 2 + wm] = mnv[ln];
            }
        }
    }
    __syncthreads();

    // final merges + global writes: threads 0-127 row-merge, 128-255 col-merge (parallel)
    if (tid < 128) {
        float v1 = -INFINITY, v2 = -INFINITY, mn = INFINITY;
        int i1 = 0x7fffffff, i2 = 0x7fffffff;
        #pragma unroll
        for (int w = 0; w < 4; w++) {
            mn = fminf(mn, smn[tid * 4 + w]);
            merge2(v1, i1, v2, i2, sv1[tid * 4 + w], si1[tid * 4 + w], sv2[tid * 4 + w], si2[tid * 4 + w]);
        }
        int r = r0 + tid;
        g_p1v[cb][r] = v1; g_p1i[cb][r] = i1;
        g_p2v[cb][r] = v2; g_p2i[cb][r] = i2;
        g_pmn[cb][r] = mn;
    } else if (rb != cb) {
        int t2 = tid - 128;
        float v1 = -INFINITY, v2 = -INFINITY, mn = INFINITY;
        int i1 = 0x7fffffff, i2 = 0x7fffffff;
        #pragma unroll
        for (int w = 0; w < 2; w++) {
            mn = fminf(mn, cmn[t2 * 2 + w]);
            merge2(v1, i1, v2, i2, cv1[t2 * 2 + w], ci1[t2 * 2 + w], cv2[t2 * 2 + w], ci2[t2 * 2 + w]);
        }
        int r = c0 + t2;
        g_p1v[rb][r] = v1; g_p1i[rb][r] = i1;
        g_p2v[rb][r] = v2; g_p2i[rb][r] = i2;
        g_pmn[rb][r] = mn;
    }
}

// ---------------- kernel 3: fused warp-per-row merge + d^2->dist + cos dots ----------------
__global__ void k_merge_alpha(const float* __restrict__ clot) {
    int t = threadIdx.x;
    int r = blockIdx.x * 8 + (t >> 5);
    int l = t & 31;
    float b1v = g_p1v[l][r]; int b1i = g_p1i[l][r];
    float b2v = g_p2v[l][r]; int b2i = g_p2i[l][r];
    float mn  = g_pmn[l][r];
    int c2 = l + 32;
    mn = fminf(mn, g_pmn[c2][r]);
    merge2(b1v, b1i, b2v, b2i, g_p1v[c2][r], g_p1i[c2][r], g_p2v[c2][r], g_p2i[c2][r]);
    #pragma unroll
    for (int off = 16; off > 0; off >>= 1) {
        float o1v = __shfl_xor_sync(0xffffffffu, b1v, off);
        int   o1i = __shfl_xor_sync(0xffffffffu, b1i, off);
        float o2v = __shfl_xor_sync(0xffffffffu, b2v, off);
        int   o2i = __shfl_xor_sync(0xffffffffu, b2i, off);
        float omn = __shfl_xor_sync(0xffffffffu, mn,  off);
        mn = fminf(mn, omn);
        merge2(b1v, b1i, b2v, b2i, o1v, o1i, o2v, o2i);
    }
    int j1 = b1i, j2 = b2i;
    const float* cr = clot + (size_t)r * DIM2;
    const float* ca = clot + (size_t)j1 * DIM2;
    const float* cb = clot + (size_t)j2 * DIM2;
    float d1 = 0.f, d2 = 0.f;
    #pragma unroll 4
    for (int k = l; k < DIM2; k += 32) {
        float c = cr[k];
        d1 = fmaf(c, ca[k], d1);
        d2 = fmaf(c, cb[k], d2);
    }
    #pragma unroll
    for (int o = 16; o > 0; o >>= 1) {
        d1 += __shfl_xor_sync(0xffffffffu, d1, o);
        d2 += __shfl_xor_sync(0xffffffffu, d2, o);
    }
    if (l == 0) {
        float ap1 = (b1v < -1e6f) ? (sqrtf(fmaxf(b1v + BIGF, 1e-12f)) - BIGF)
                                  : sqrtf(fmaxf(b1v, 1e-12f));
        float ap2 = (b2v < -1e6f) ? (sqrtf(fmaxf(b2v + BIGF, 1e-12f)) - BIGF)
                                  : sqrtf(fmaxf(b2v, 1e-12f));
        float an  = (mn > 1e6f) ? (sqrtf(fmaxf(mn - BIGF, 1e-12f)) + BIGF)
                                : sqrtf(fmaxf(mn, 1e-12f));
        g_ap1[r] = ap1; g_ap2[r] = ap2; g_an[r] = an;
        g_a1[r] = d1 / (g_nrm[r] * g_nrm[j1]);
        g_a2[r] = d2 / (g_nrm[r] * g_nrm[j2]);
    }
}

// ---------------- kernel 4a: per-block loss partials ----------------
__global__ void k_final_part() {
    int t = threadIdx.x;
    int r = blockIdx.x * 256 + t;
    float ap1 = g_ap1[r], ap2 = g_ap2[r], an = g_an[r];
    float a1 = g_a1[r], a2 = g_a2[r];
    float y  = (a1 < a2) ? -1.f : 1.f;
    float ym = (a1 == a2) ? 0.f : 1.f;
    float x1 = ap2 * ym;
    float x2 = ap1 * ym + MARGINF * (a1 - a2 - y);
    float t11 = fmaxf(0.f, -y * (x1 - x2) + MARGINF);
    float ap1m = ap1 + MARGINF * (a1 - 1.f);
    float t13 = fmaxf(0.f, -(an - ap1m) + MARGINF);
    float tp = (an > ap1m) ? 1.f : 0.f;
    #pragma unroll
    for (int o = 16; o > 0; o >>= 1) {
        t11 += __shfl_xor_sync(0xffffffffu, t11, o);
        t13 += __shfl_xor_sync(0xffffffffu, t13, o);
        tp  += __shfl_xor_sync(0xffffffffu, tp,  o);
    }
    __shared__ float s1[8], s2[8], s3[8];
    int w = t >> 5, l = t & 31;
    if (l == 0) { s1[w] = t11; s2[w] = t13; s3[w] = tp; }
    __syncthreads();
    if (t == 0) {
        float a = 0.f, b = 0.f, c = 0.f;
        #pragma unroll
        for (int i = 0; i < 8; i++) { a += s1[i]; b += s2[i]; c += s3[i]; }
        g_fin[blockIdx.x][0] = a;
        g_fin[blockIdx.x][1] = b;
        g_fin[blockIdx.x][2] = c;
    }
}

// ---------------- kernel 4b: combine 32 partials ----------------
__global__ void k_final2(float* __restrict__ out) {
    int t = threadIdx.x;  // 32 threads
    float a = g_fin[t][0], b = g_fin[t][1], c = g_fin[t][2];
    #pragma unroll
    for (int o = 16; o > 0; o >>= 1) {
        a += __shfl_xor_sync(0xffffffffu, a, o);
        b += __shfl_xor_sync(0xffffffffu, b, o);
        c += __shfl_xor_sync(0xffffffffu, c, o);
    }
    if (t == 0) {
        out[0] = 0.1f * (a / (float)NROW) + (b / (float)NROW);
        out[1] = c / (float)NROW;
    }
}

// ---------------- launch ----------------
extern "C" void kernel_launch(void* const* d_in, const int* in_sizes, int n_in,
                              void* d_out, int out_size) {
    const float* emb  = (const float*)d_in[0];
    const void*  lab  = d_in[1];
    const float* clot = (const float*)d_in[2];
    float* out = (float*)d_out;

    cudaFuncSetAttribute(k_dist_mma, cudaFuncAttributeMaxDynamicSharedMemorySize, SMEM_TOTAL);

    k_prep<<<NROW, 256>>>(emb, clot, lab);
    k_dist_mma<<<NTILE, 256, SMEM_TOTAL>>>(lab);
    k_merge_alpha<<<NROW / 8, 256>>>(clot);
    k_final_part<<<32, 256>>>();
    k_final2<<<1, 32>>>(out);
}

// round 16
// speedup vs baseline: 1.2620x; 1.0061x over previous
#include <cuda_runtime.h>
#include <cuda_fp16.h>
#include <math.h>
#include <stdint.h>

#define NROW 8192
#define DIM 1024
#define DIM2 512
#define BM 128
#define BN 128
#define NCT (NROW / BN)            // 64 partial slots
#define NOFFD 2016                 // strictly-upper full tiles
#define NGRID 2144                 // 2016 full + 128 diagonal half-tiles
#define BIGF 9999999.0f
#define MARGINF 0.3f

#define STAGE_BYTES 32768          // A (<=128x128B) + B (128x128B), K=64 halfs
#define B_OFF 16384
#define NSTG 3
#define SMEM_TOTAL (NSTG * STAGE_BYTES)   // 96 KB
#define NSTAGES_K 16               // 1024 / 64

// ---------------- device scratch ----------------
__device__ int   g_lab64;
__device__ float g_sq[NROW];
__device__ float g_nrm[NROW];
__device__ __half g_hi[(size_t)NROW * DIM];
__device__ float g_p1v[NCT][NROW];
__device__ float g_p2v[NCT][NROW];
__device__ int   g_p1i[NCT][NROW];
__device__ int   g_p2i[NCT][NROW];
__device__ float g_pmn[NCT][NROW];
__device__ float g_ap1[NROW], g_ap2[NROW], g_an[NROW];
__device__ float g_a1[NROW], g_a2[NROW];
__device__ float g_fin[32][3];

// ---------------- helpers ----------------
__device__ __forceinline__ uint32_t smem_u32(const void* p) {
    uint32_t a;
    asm("{ .reg .u64 t; cvta.to.shared.u64 t, %1; cvt.u32.u64 %0, t; }" : "=r"(a) : "l"(p));
    return a;
}
__device__ __forceinline__ void cpasync16(uint32_t dst, const void* src) {
    asm volatile("cp.async.cg.shared.global [%0], [%1], 16;" :: "r"(dst), "l"(src));
}
#define CP_COMMIT() asm volatile("cp.async.commit_group;" ::: "memory")
#define CP_WAIT1()  asm volatile("cp.async.wait_group 1;" ::: "memory")
#define CP_WAIT0()  asm volatile("cp.async.wait_group 0;" ::: "memory")

#define LDM4(r, addr) \
    asm volatile("ldmatrix.sync.aligned.m8n8.x4.shared.b16 {%0,%1,%2,%3}, [%4];" \
        : "=r"((r)[0]), "=r"((r)[1]), "=r"((r)[2]), "=r"((r)[3]) : "r"(addr))

#define MMA16816(c, a, b0_, b1_) \
    asm volatile("mma.sync.aligned.m16n8k16.row.col.f32.f16.f16.f32 " \
        "{%0,%1,%2,%3}, {%4,%5,%6,%7}, {%8,%9}, {%0,%1,%2,%3};" \
        : "+f"((c)[0]), "+f"((c)[1]), "+f"((c)[2]), "+f"((c)[3]) \
        : "r"((a)[0]), "r"((a)[1]), "r"((a)[2]), "r"((a)[3]), "r"(b0_), "r"(b1_))

__device__ __forceinline__ int getlab(const void* lab, int i, int is64) {
    if (is64) return (int)((const long long*)lab)[i];
    return ((const int*)lab)[i];
}
__device__ __forceinline__ bool keybetter(float av, int ai, float bv, int bi) {
    return (av > bv) || (av == bv && ai < bi);
}
__device__ __forceinline__ uint32_t sw128(uint32_t off) { return off ^ ((off >> 3) & 0x70u); }

__device__ __forceinline__ void merge2(float& v1, int& i1, float& v2, int& i2,
                                       float o1v, int o1i, float o2v, int o2i) {
    if (keybetter(o1v, o1i, v1, i1)) {
        if (keybetter(v1, i1, o2v, o2i)) { v2 = v1; i2 = i1; }
        else                             { v2 = o2v; i2 = o2i; }
        v1 = o1v; i1 = o1i;
    } else if (keybetter(o1v, o1i, v2, i2)) { v2 = o1v; i2 = o1i; }
}

// ---------------- kernel 1: fused detect + norms + fp16 convert ----------------
__global__ void k_prep(const float* __restrict__ emb, const float* __restrict__ clot,
                       const void* __restrict__ lab) {
    int r = blockIdx.x, t = threadIdx.x;
    int lane = t & 31, w = t >> 5;
    if (r == 0 && t == 0) {
        const unsigned* p = (const unsigned*)lab;
        int is64 = 1;
        for (int i = 0; i < 64; i++) if (p[2 * i + 1] != 0u) { is64 = 0; break; }
        g_lab64 = is64;
    }
    float4 v = ((const float4*)(emb + (size_t)r * DIM))[t];
    float s = v.x * v.x + v.y * v.y + v.z * v.z + v.w * v.w;
    size_t o = (size_t)r * DIM + t * 4;
    *(__half2*)(g_hi + o)     = __half2(__float2half(v.x), __float2half(v.y));
    *(__half2*)(g_hi + o + 2) = __half2(__float2half(v.z), __float2half(v.w));
    float c = 0.f;
    if (t < DIM2 / 4) {
        float4 wv = ((const float4*)(clot + (size_t)r * DIM2))[t];
        c = wv.x * wv.x + wv.y * wv.y + wv.z * wv.z + wv.w * wv.w;
    }
    #pragma unroll
    for (int o2 = 16; o2 > 0; o2 >>= 1) {
        s += __shfl_xor_sync(0xffffffffu, s, o2);
        c += __shfl_xor_sync(0xffffffffu, c, o2);
    }
    __shared__ float se[8], sc[8];
    if (lane == 0) { se[w] = s; sc[w] = c; }
    __syncthreads();
    if (t == 0) {
        float ss = 0.f, cc = 0.f;
        #pragma unroll
        for (int i = 0; i < 8; i++) { ss += se[i]; cc += sc[i]; }
        g_sq[r] = ss; g_nrm[r] = sqrtf(cc);
    }
}

// ---------------- kernel 2: fp16 HMMA GEMM ----------------
// ids [0,2016): full 128x128 off-diag tiles (row+col harvest).
// ids [2016,2144): diagonal tiles split into 64-row halves (row harvest only).
__global__ __launch_bounds__(256, 2) void k_dist_mma(const void* __restrict__ lab) {
    extern __shared__ char smem[];
    const uint32_t sb = smem_u32(smem);
    const int tid = threadIdx.x;
    const int lane = tid & 31, wid = tid >> 5;
    const int lab64 = g_lab64;
    const int tg = lane & 3, g = lane >> 2;
    const int krot = wid & 3;

    if (blockIdx.x >= NOFFD) {
        // ================= diagonal half-tile path (BM=64 x BN=128) =================
        int u = blockIdx.x - NOFFD;      // 0..127
        int b = u >> 1, h = u & 1;
        const int r0h = b * 128 + h * 64;
        const int c0 = b * 128;
        const int wm = wid >> 1, wn = wid & 1;   // 4 x 2 warps, 16row x 64col tiles

        // loader: A 512 ops (2/thread), B 1024 ops (4/thread)
        const char* srcp[6];
        uint32_t dsto[6];
        #pragma unroll
        for (int v = 0; v < 2; v++) {
            int i = tid + v * 256;
            int row = i >> 3, seg = i & 7;
            srcp[v] = (const char*)(g_hi + (size_t)(r0h + row) * DIM + seg * 8);
            dsto[v] = sw128((uint32_t)row * 128u + (uint32_t)seg * 16u);
        }
        #pragma unroll
        for (int v = 2; v < 6; v++) {
            int j = tid + (v - 2) * 256;
            int row = j >> 3, seg = j & 7;
            srcp[v] = (const char*)(g_hi + (size_t)(c0 + row) * DIM + seg * 8);
            dsto[v] = B_OFF + sw128((uint32_t)row * 128u + (uint32_t)seg * 16u);
        }

        // ldmatrix offsets
        uint32_t preA, mskA, preB[4], mskB[4];
        {
            int rA = wm * 16 + (lane & 15);
            int sA = lane >> 4;
            uint32_t p = (uint32_t)rA * 128u + (uint32_t)sA * 16u;
            mskA = (p >> 3) & 0x70u; preA = p;
            int rB = wn * 64 + ((lane >> 4) << 3) + (lane & 7);
            int sB = (lane >> 3) & 1;
            #pragma unroll
            for (int np = 0; np < 4; np++) {
                uint32_t q = (uint32_t)(rB + np * 16) * 128u + (uint32_t)sB * 16u;
                mskB[np] = (q >> 3) & 0x70u; preB[np] = q;
            }
        }

        float acc[8][4];
        #pragma unroll
        for (int a = 0; a < 8; a++)
            #pragma unroll
            for (int c = 0; c < 4; c++) acc[a][c] = 0.f;

        #pragma unroll
        for (int p = 0; p < 2; p++) {
            uint32_t db = sb + (uint32_t)p * STAGE_BYTES;
            #pragma unroll
            for (int v = 0; v < 6; v++) cpasync16(db + dsto[v], srcp[v] + (size_t)p * 128);
            CP_COMMIT();
        }
        int buf = 0, pbuf = 2;
        for (int s = 0; s < NSTAGES_K; s++) {
            CP_WAIT1();
            __syncthreads();
            {
                int sn = s + 2;
                if (sn < NSTAGES_K) {
                    uint32_t db = sb + (uint32_t)pbuf * STAGE_BYTES;
                    #pragma unroll
                    for (int v = 0; v < 6; v++) cpasync16(db + dsto[v], srcp[v] + (size_t)sn * 128);
                }
                CP_COMMIT();
            }
            const uint32_t base = sb + (uint32_t)buf * STAGE_BYTES;
            const uint32_t baseB = base + B_OFF;
            if (++buf == NSTG) buf = 0;
            if (++pbuf == NSTG) pbuf = 0;

            #pragma unroll
            for (int kci = 0; kci < 4; kci++) {
                const int kc = (kci + krot) & 3;
                const uint32_t kd = (uint32_t)kc * 32u;
                uint32_t BH[4][4];
                #pragma unroll
                for (int np = 0; np < 4; np++)
                    LDM4(BH[np], baseB + ((preB[np] + kd) ^ mskB[np]));
                uint32_t AH[4];
                LDM4(AH, base + ((preA + kd) ^ mskA));
                #pragma unroll
                for (int nt = 0; nt < 8; nt++)
                    MMA16816(acc[nt], AH, BH[nt >> 1][(nt & 1) * 2], BH[nt >> 1][(nt & 1) * 2 + 1]);
            }
        }

        // epilogue loads (before drain)
        float sqj[16]; int labj[16];
        #pragma unroll
        for (int ln = 0; ln < 16; ln++) {
            int cc = c0 + wn * 64 + (ln >> 1) * 8 + tg * 2 + (ln & 1);
            sqj[ln] = g_sq[cc];
            labj[ln] = getlab(lab, cc, lab64);
        }
        float sqi[2]; int labi[2];
        #pragma unroll
        for (int lm = 0; lm < 2; lm++) {
            int m = r0h + wm * 16 + g + lm * 8;
            sqi[lm] = g_sq[m];
            labi[lm] = getlab(lab, m, lab64);
        }
        CP_WAIT0();
        __syncthreads();

        float* sv1 = (float*)smem;            // [64][2]
        float* sv2 = (float*)(smem + 512);
        float* smn = (float*)(smem + 1024);
        int*   si1 = (int*)(smem + 1536);
        int*   si2 = (int*)(smem + 2048);

        float b1v[2], b2v[2], mnv[2]; int b1i[2], b2i[2];
        #pragma unroll
        for (int lm = 0; lm < 2; lm++) {
            float v1 = -INFINITY, v2 = -INFINITY, mn = INFINITY;
            int i1 = 0x7fffffff, i2 = 0x7fffffff;
            #pragma unroll
            for (int ln = 0; ln < 16; ln++) {
                int col = c0 + wn * 64 + (ln >> 1) * 8 + tg * 2 + (ln & 1);
                float d2 = fmaf(-2.0f, acc[ln >> 1][lm * 2 + (ln & 1)], sqi[lm] + sqj[ln]);
                bool same = (labi[lm] == labj[ln]);
                float pv = same ? d2 : d2 - BIGF;
                float nv = same ? d2 + BIGF : d2;
                mn = fminf(mn, nv);
                if (keybetter(pv, col, v1, i1)) { v2 = v1; i2 = i1; v1 = pv; i1 = col; }
                else if (keybetter(pv, col, v2, i2)) { v2 = pv; i2 = col; }
            }
            b1v[lm] = v1; b1i[lm] = i1; b2v[lm] = v2; b2i[lm] = i2; mnv[lm] = mn;
        }
        #pragma unroll
        for (int lm = 0; lm < 2; lm++) {
            #pragma unroll
            for (int off = 1; off <= 2; off <<= 1) {
                float o1v = __shfl_xor_sync(0xffffffffu, b1v[lm], off);
                int   o1i = __shfl_xor_sync(0xffffffffu, b1i[lm], off);
                float o2v = __shfl_xor_sync(0xffffffffu, b2v[lm], off);
                int   o2i = __shfl_xor_sync(0xffffffffu, b2i[lm], off);
                float omn = __shfl_xor_sync(0xffffffffu, mnv[lm], off);
                mnv[lm] = fminf(mnv[lm], omn);
                merge2(b1v[lm], b1i[lm], b2v[lm], b2i[lm], o1v, o1i, o2v, o2i);
            }
        }
        if (tg == 0) {
            #pragma unroll
            for (int lm = 0; lm < 2; lm++) {
                int rl = wm * 16 + g + lm * 8;
                sv1[rl * 2 + wn] = b1v[lm]; si1[rl * 2 + wn] = b1i[lm];
                sv2[rl * 2 + wn] = b2v[lm]; si2[rl * 2 + wn] = b2i[lm];
                smn[rl * 2 + wn] = mnv[lm];
            }
        }
        __syncthreads();
        if (tid < 64) {
            float v1 = -INFINITY, v2 = -INFINITY, mn = INFINITY;
            int i1 = 0x7fffffff, i2 = 0x7fffffff;
            #pragma unroll
            for (int w = 0; w < 2; w++) {
                mn = fminf(mn, smn[tid * 2 + w]);
                merge2(v1, i1, v2, i2, sv1[tid * 2 + w], si1[tid * 2 + w], sv2[tid * 2 + w], si2[tid * 2 + w]);
            }
            int r = r0h + tid;
            g_p1v[b][r] = v1; g_p1i[b][r] = i1;
            g_p2v[b][r] = v2; g_p2i[b][r] = i2;
            g_pmn[b][r] = mn;
        }
        return;
    }

    // ================= full off-diagonal tile path (unchanged) =================
    const int wm = wid >> 2, wn = wid & 3;
    int rb, cb;
    {
        int u = blockIdx.x; rb = 0;
        while (u >= 63 - rb) { u -= 63 - rb; rb++; }
        cb = rb + 1 + u;
    }
    const int r0 = rb * BM, c0 = cb * BN;

    const char* srcp[8];
    uint32_t dsto[8];
    #pragma unroll
    for (int v = 0; v < 4; v++) {
        int i = tid + v * 256;
        int row = i >> 3, seg = i & 7;
        srcp[v] = (const char*)(g_hi + (size_t)(r0 + row) * DIM + seg * 8);
        dsto[v] = sw128((uint32_t)row * 128u + (uint32_t)seg * 16u);
    }
    #pragma unroll
    for (int v = 4; v < 8; v++) {
        int j = tid + (v - 4) * 256;
        int row = j >> 3, seg = j & 7;
        srcp[v] = (const char*)(g_hi + (size_t)(c0 + row) * DIM + seg * 8);
        dsto[v] = B_OFF + sw128((uint32_t)row * 128u + (uint32_t)seg * 16u);
    }

    uint32_t preA[4], mskA[4], preB[2], mskB[2];
    {
        int rA = wm * 64 + (lane & 15);
        int sA = lane >> 4;
        #pragma unroll
        for (int mt = 0; mt < 4; mt++) {
            uint32_t p = (uint32_t)(rA + mt * 16) * 128u + (uint32_t)sA * 16u;
            mskA[mt] = (p >> 3) & 0x70u;
            preA[mt] = p;
        }
        int rB = wn * 32 + ((lane >> 4) << 3) + (lane & 7);
        int sB = (lane >> 3) & 1;
        #pragma unroll
        for (int np = 0; np < 2; np++) {
            uint32_t p = (uint32_t)(rB + np * 16) * 128u + (uint32_t)sB * 16u;
            mskB[np] = (p >> 3) & 0x70u;
            preB[np] = p;
        }
    }

    float acc[4][4][4];
    #pragma unroll
    for (int a = 0; a < 4; a++)
        #pragma unroll
        for (int b2 = 0; b2 < 4; b2++)
            #pragma unroll
            for (int c = 0; c < 4; c++) acc[a][b2][c] = 0.f;

    #pragma unroll
    for (int p = 0; p < 2; p++) {
        uint32_t db = sb + (uint32_t)p * STAGE_BYTES;
        #pragma unroll
        for (int v = 0; v < 8; v++) cpasync16(db + dsto[v], srcp[v] + (size_t)p * 128);
        CP_COMMIT();
    }

    int buf = 0, pbuf = 2;
    for (int s = 0; s < NSTAGES_K; s++) {
        CP_WAIT1();
        __syncthreads();
        {
            int sn = s + 2;
            if (sn < NSTAGES_K) {
                uint32_t db = sb + (uint32_t)pbuf * STAGE_BYTES;
                #pragma unroll
                for (int v = 0; v < 8; v++) cpasync16(db + dsto[v], srcp[v] + (size_t)sn * 128);
            }
            CP_COMMIT();
        }
        const uint32_t base = sb + (uint32_t)buf * STAGE_BYTES;
        const uint32_t baseB = base + B_OFF;
        if (++buf == NSTG) buf = 0;
        if (++pbuf == NSTG) pbuf = 0;

        #pragma unroll
        for (int kci = 0; kci < 4; kci++) {
            const int kc = (kci + krot) & 3;
            const uint32_t kd = (uint32_t)kc * 32u;
            uint32_t BH[2][4];
            #pragma unroll
            for (int np = 0; np < 2; np++)
                LDM4(BH[np], baseB + ((preB[np] + kd) ^ mskB[np]));
            uint32_t AH[4][4];
            #pragma unroll
            for (int mt = 0; mt < 4; mt++)
                LDM4(AH[mt], base + ((preA[mt] + kd) ^ mskA[mt]));
            #pragma unroll
            for (int mt = 0; mt < 4; mt++)
                #pragma unroll
                for (int nt = 0; nt < 4; nt++)
                    MMA16816(acc[mt][nt], AH[mt], BH[nt >> 1][(nt & 1) * 2], BH[nt >> 1][(nt & 1) * 2 + 1]);
        }
    }

    float sqj[8]; int labj[8];
    #pragma unroll
    for (int ln = 0; ln < 8; ln++) {
        int cc = c0 + wn * 32 + (ln >> 1) * 8 + tg * 2 + (ln & 1);
        sqj[ln] = g_sq[cc];
        labj[ln] = getlab(lab, cc, lab64);
    }
    float sqi[8]; int labi[8];
    #pragma unroll
    for (int lm = 0; lm < 8; lm++) {
        int m = r0 + wm * 64 + (lm >> 1) * 16 + g + (lm & 1) * 8;
        sqi[lm] = g_sq[m];
        labi[lm] = getlab(lab, m, lab64);
    }

    CP_WAIT0();
    __syncthreads();

    float* sv1 = (float*)smem;              // [128][4]
    float* sv2 = (float*)(smem + 2048);
    float* smn = (float*)(smem + 4096);
    int*   si1 = (int*)(smem + 6144);
    int*   si2 = (int*)(smem + 8192);
    float* cv1 = (float*)(smem + 16384);    // [128][2]
    float* cv2 = (float*)(smem + 17408);
    float* cmn = (float*)(smem + 18432);
    int*   ci1 = (int*)(smem + 19456);
    int*   ci2 = (int*)(smem + 20480);

    {
        float b1v[8], b2v[8], mnv[8]; int b1i[8], b2i[8];
        #pragma unroll
        for (int lm = 0; lm < 8; lm++) {
            float v1 = -INFINITY, v2 = -INFINITY, mn = INFINITY;
            int i1 = 0x7fffffff, i2 = 0x7fffffff;
            #pragma unroll
            for (int ln = 0; ln < 8; ln++) {
                int col = c0 + wn * 32 + (ln >> 1) * 8 + tg * 2 + (ln & 1);
                float& ar = acc[lm >> 1][ln >> 1][(lm & 1) * 2 + (ln & 1)];
                float d2 = fmaf(-2.0f, ar, sqi[lm] + sqj[ln]);
                ar = d2;
                bool same = (labi[lm] == labj[ln]);
                float pv = same ? d2 : d2 - BIGF;
                float nv = same ? d2 + BIGF : d2;
                mn = fminf(mn, nv);
                if (keybetter(pv, col, v1, i1)) { v2 = v1; i2 = i1; v1 = pv; i1 = col; }
                else if (keybetter(pv, col, v2, i2)) { v2 = pv; i2 = col; }
            }
            b1v[lm] = v1; b1i[lm] = i1; b2v[lm] = v2; b2i[lm] = i2; mnv[lm] = mn;
        }
        #pragma unroll
        for (int lm = 0; lm < 8; lm++) {
            #pragma unroll
            for (int off = 1; off <= 2; off <<= 1) {
                float o1v = __shfl_xor_sync(0xffffffffu, b1v[lm], off);
                int   o1i = __shfl_xor_sync(0xffffffffu, b1i[lm], off);
                float o2v = __shfl_xor_sync(0xffffffffu, b2v[lm], off);
                int   o2i = __shfl_xor_sync(0xffffffffu, b2i[lm], off);
                float omn = __shfl_xor_sync(0xffffffffu, mnv[lm], off);
                mnv[lm] = fminf(mnv[lm], omn);
                merge2(b1v[lm], b1i[lm], b2v[lm], b2i[lm], o1v, o1i, o2v, o2i);
            }
        }
        if (tg == 0) {
            #pragma unroll
            for (int lm = 0; lm < 8; lm++) {
                int rl = wm * 64 + (lm >> 1) * 16 + g + (lm & 1) * 8;
                sv1[rl * 4 + wn] = b1v[lm]; si1[rl * 4 + wn] = b1i[lm];
                sv2[rl * 4 + wn] = b2v[lm]; si2[rl * 4 + wn] = b2i[lm];
                smn[rl * 4 + wn] = mnv[lm];
            }
        }
    }

    {
        float b1v[8], b2v[8], mnv[8]; int b1i[8], b2i[8];
        #pragma unroll
        for (int ln = 0; ln < 8; ln++) {
            float v1 = -INFINITY, v2 = -INFINITY, mn = INFINITY;
            int i1 = 0x7fffffff, i2 = 0x7fffffff;
            #pragma unroll
            for (int lm = 0; lm < 8; lm++) {
                int rowidx = r0 + wm * 64 + (lm >> 1) * 16 + g + (lm & 1) * 8;
                float d2 = acc[lm >> 1][ln >> 1][(lm & 1) * 2 + (ln & 1)];
                bool same = (labi[lm] == labj[ln]);
                float pv = same ? d2 : d2 - BIGF;
                float nv = same ? d2 + BIGF : d2;
                mn = fminf(mn, nv);
                if (keybetter(pv, rowidx, v1, i1)) { v2 = v1; i2 = i1; v1 = pv; i1 = rowidx; }
                else if (keybetter(pv, rowidx, v2, i2)) { v2 = pv; i2 = rowidx; }
            }
            b1v[ln] = v1; b1i[ln] = i1; b2v[ln] = v2; b2i[ln] = i2; mnv[ln] = mn;
        }
        #pragma unroll
        for (int ln = 0; ln < 8; ln++) {
            #pragma unroll
            for (int off = 4; off <= 16; off <<= 1) {
                float o1v = __shfl_xor_sync(0xffffffffu, b1v[ln], off);
                int   o1i = __shfl_xor_sync(0xffffffffu, b1i[ln], off);
                float o2v = __shfl_xor_sync(0xffffffffu, b2v[ln], off);
                int   o2i = __shfl_xor_sync(0xffffffffu, b2i[ln], off);
                float omn = __shfl_xor_sync(0xffffffffu, mnv[ln], off);
                mnv[ln] = fminf(mnv[ln], omn);
                merge2(b1v[ln], b1i[ln], b2v[ln], b2i[ln], o1v, o1i, o2v, o2i);
            }
        }
        if (g == 0) {
            #pragma unroll
            for (int ln = 0; ln < 8; ln++) {
                int cl = wn * 32 + (ln >> 1) * 8 + tg * 2 + (ln & 1);
                cv1[cl * 2 + wm] = b1v[ln]; ci1[cl * 2 + wm] = b1i[ln];
                cv2[cl * 2 + wm] = b2v[ln]; ci2[cl * 2 + wm] = b2i[ln];
                cmn[cl * 2 + wm] = mnv[ln];
            }
        }
    }
    __syncthreads();

    if (tid < 128) {
        float v1 = -INFINITY, v2 = -INFINITY, mn = INFINITY;
        int i1 = 0x7fffffff, i2 = 0x7fffffff;
        #pragma unroll
        for (int w = 0; w < 4; w++) {
            mn = fminf(mn, smn[tid * 4 + w]);
            merge2(v1, i1, v2, i2, sv1[tid * 4 + w], si1[tid * 4 + w], sv2[tid * 4 + w], si2[tid * 4 + w]);
        }
        int r = r0 + tid;
        g_p1v[cb][r] = v1; g_p1i[cb][r] = i1;
        g_p2v[cb][r] = v2; g_p2i[cb][r] = i2;
        g_pmn[cb][r] = mn;
    } else {
        int t2 = tid - 128;
        float v1 = -INFINITY, v2 = -INFINITY, mn = INFINITY;
        int i1 = 0x7fffffff, i2 = 0x7fffffff;
        #pragma unroll
        for (int w = 0; w < 2; w++) {
            mn = fminf(mn, cmn[t2 * 2 + w]);
            merge2(v1, i1, v2, i2, cv1[t2 * 2 + w], ci1[t2 * 2 + w], cv2[t2 * 2 + w], ci2[t2 * 2 + w]);
        }
        int r = c0 + t2;
        g_p1v[rb][r] = v1; g_p1i[rb][r] = i1;
        g_p2v[rb][r] = v2; g_p2i[rb][r] = i2;
        g_pmn[rb][r] = mn;
    }
}

// ---------------- kernel 3: fused warp-per-row merge + d^2->dist + cos dots ----------------
__global__ void k_merge_alpha(const float* __restrict__ clot) {
    int t = threadIdx.x;
    int r = blockIdx.x * 8 + (t >> 5);
    int l = t & 31;
    float b1v = g_p1v[l][r]; int b1i = g_p1i[l][r];
    float b2v = g_p2v[l][r]; int b2i = g_p2i[l][r];
    float mn  = g_pmn[l][r];
    int c2 = l + 32;
    mn = fminf(mn, g_pmn[c2][r]);
    merge2(b1v, b1i, b2v, b2i, g_p1v[c2][r], g_p1i[c2][r], g_p2v[c2][r], g_p2i[c2][r]);
    #pragma unroll
    for (int off = 16; off > 0; off >>= 1) {
        float o1v = __shfl_xor_sync(0xffffffffu, b1v, off);
        int   o1i = __shfl_xor_sync(0xffffffffu, b1i, off);
        float o2v = __shfl_xor_sync(0xffffffffu, b2v, off);
        int   o2i = __shfl_xor_sync(0xffffffffu, b2i, off);
        float omn = __shfl_xor_sync(0xffffffffu, mn,  off);
        mn = fminf(mn, omn);
        merge2(b1v, b1i, b2v, b2i, o1v, o1i, o2v, o2i);
    }
    int j1 = b1i, j2 = b2i;
    const float* cr = clot + (size_t)r * DIM2;
    const float* ca = clot + (size_t)j1 * DIM2;
    const float* cb = clot + (size_t)j2 * DIM2;
    float d1 = 0.f, d2 = 0.f;
    #pragma unroll 4
    for (int k = l; k < DIM2; k += 32) {
        float c = cr[k];
        d1 = fmaf(c, ca[k], d1);
        d2 = fmaf(c, cb[k], d2);
    }
    #pragma unroll
    for (int o = 16; o > 0; o >>= 1) {
        d1 += __shfl_xor_sync(0xffffffffu, d1, o);
        d2 += __shfl_xor_sync(0xffffffffu, d2, o);
    }
    if (l == 0) {
        float ap1 = (b1v < -1e6f) ? (sqrtf(fmaxf(b1v + BIGF, 1e-12f)) - BIGF)
                                  : sqrtf(fmaxf(b1v, 1e-12f));
        float ap2 = (b2v < -1e6f) ? (sqrtf(fmaxf(b2v + BIGF, 1e-12f)) - BIGF)
                                  : sqrtf(fmaxf(b2v, 1e-12f));
        float an  = (mn > 1e6f) ? (sqrtf(fmaxf(mn - BIGF, 1e-12f)) + BIGF)
                                : sqrtf(fmaxf(mn, 1e-12f));
        g_ap1[r] = ap1; g_ap2[r] = ap2; g_an[r] = an;
        g_a1[r] = d1 / (g_nrm[r] * g_nrm[j1]);
        g_a2[r] = d2 / (g_nrm[r] * g_nrm[j2]);
    }
}

// ---------------- kernel 4a: per-block loss partials ----------------
__global__ void k_final_part() {
    int t = threadIdx.x;
    int r = blockIdx.x * 256 + t;
    float ap1 = g_ap1[r], ap2 = g_ap2[r], an = g_an[r];
    float a1 = g_a1[r], a2 = g_a2[r];
    float y  = (a1 < a2) ? -1.f : 1.f;
    float ym = (a1 == a2) ? 0.f : 1.f;
    float x1 = ap2 * ym;
    float x2 = ap1 * ym + MARGINF * (a1 - a2 - y);
    float t11 = fmaxf(0.f, -y * (x1 - x2) + MARGINF);
    float ap1m = ap1 + MARGINF * (a1 - 1.f);
    float t13 = fmaxf(0.f, -(an - ap1m) + MARGINF);
    float tp = (an > ap1m) ? 1.f : 0.f;
    #pragma unroll
    for (int o = 16; o > 0; o >>= 1) {
        t11 += __shfl_xor_sync(0xffffffffu, t11, o);
        t13 += __shfl_xor_sync(0xffffffffu, t13, o);
        tp  += __shfl_xor_sync(0xffffffffu, tp,  o);
    }
    __shared__ float s1[8], s2[8], s3[8];
    int w = t >> 5, l = t & 31;
    if (l == 0) { s1[w] = t11; s2[w] = t13; s3[w] = tp; }
    __syncthreads();
    if (t == 0) {
        float a = 0.f, b = 0.f, c = 0.f;
        #pragma unroll
        for (int i = 0; i < 8; i++) { a += s1[i]; b += s2[i]; c += s3[i]; }
        g_fin[blockIdx.x][0] = a;
        g_fin[blockIdx.x][1] = b;
        g_fin[blockIdx.x][2] = c;
    }
}

// ---------------- kernel 4b: combine 32 partials ----------------
__global__ void k_final2(float* __restrict__ out) {
    int t = threadIdx.x;  // 32 threads
    float a = g_fin[t][0], b = g_fin[t][1], c = g_fin[t][2];
    #pragma unroll
    for (int o = 16; o > 0; o >>= 1) {
        a += __shfl_xor_sync(0xffffffffu, a, o);
        b += __shfl_xor_sync(0xffffffffu, b, o);
        c += __shfl_xor_sync(0xffffffffu, c, o);
    }
    if (t == 0) {
        out[0] = 0.1f * (a / (float)NROW) + (b / (float)NROW);
        out[1] = c / (float)NROW;
    }
}

// ---------------- launch ----------------
extern "C" void kernel_launch(void* const* d_in, const int* in_sizes, int n_in,
                              void* d_out, int out_size) {
    const float* emb  = (const float*)d_in[0];
    const void*  lab  = d_in[1];
    const float* clot = (const float*)d_in[2];
    float* out = (float*)d_out;

    cudaFuncSetAttribute(k_dist_mma, cudaFuncAttributeMaxDynamicSharedMemorySize, SMEM_TOTAL);

    k_prep<<<NROW, 256>>>(emb, clot, lab);
    k_dist_mma<<<NGRID, 256, SMEM_TOTAL>>>(lab);
    k_merge_alpha<<<NROW / 8, 256>>>(clot);
    k_final_part<<<32, 256>>>();
    k_final2<<<1, 32>>>(out);
}

// round 17
// speedup vs baseline: 1.2627x; 1.0006x over previous
#include <cuda_runtime.h>
#include <cuda_fp16.h>
#include <math.h>
#include <stdint.h>

#define NROW 8192
#define DIM 1024
#define DIM2 512
#define BM 128
#define BN 128
#define NCT (NROW / BN)            // 64 partial slots
#define NOFFD 2016                 // strictly-upper full tiles
#define NGRID 2144                 // 2016 full + 128 diagonal half-tiles
#define BIGF 9999999.0f
#define MARGINF 0.3f

#define STAGE_BYTES 32768          // A (<=128x128B) + B (128x128B), K=64 halfs
#define B_OFF 16384
#define NSTG 3
#define SMEM_TOTAL (NSTG * STAGE_BYTES)   // 96 KB
#define NSTAGES_K 16               // 1024 / 64

// ---------------- device scratch ----------------
__device__ int   g_lab64;
__device__ float g_sq[NROW];
__device__ float g_nrm[NROW];
__device__ __half g_hi[(size_t)NROW * DIM];
__device__ float g_p1v[NCT][NROW];
__device__ float g_p2v[NCT][NROW];
__device__ int   g_p1i[NCT][NROW];
__device__ int   g_p2i[NCT][NROW];
__device__ float g_pmn[NCT][NROW];
__device__ float g_fin[NROW / 8][3];

// ---------------- helpers ----------------
__device__ __forceinline__ uint32_t smem_u32(const void* p) {
    uint32_t a;
    asm("{ .reg .u64 t; cvta.to.shared.u64 t, %1; cvt.u32.u64 %0, t; }" : "=r"(a) : "l"(p));
    return a;
}
__device__ __forceinline__ void cpasync16(uint32_t dst, const void* src) {
    asm volatile("cp.async.cg.shared.global [%0], [%1], 16;" :: "r"(dst), "l"(src));
}
#define CP_COMMIT() asm volatile("cp.async.commit_group;" ::: "memory")
#define CP_WAIT1()  asm volatile("cp.async.wait_group 1;" ::: "memory")
#define CP_WAIT0()  asm volatile("cp.async.wait_group 0;" ::: "memory")

#define LDM4(r, addr) \
    asm volatile("ldmatrix.sync.aligned.m8n8.x4.shared.b16 {%0,%1,%2,%3}, [%4];" \
        : "=r"((r)[0]), "=r"((r)[1]), "=r"((r)[2]), "=r"((r)[3]) : "r"(addr))

#define MMA16816(c, a, b0_, b1_) \
    asm volatile("mma.sync.aligned.m16n8k16.row.col.f32.f16.f16.f32 " \
        "{%0,%1,%2,%3}, {%4,%5,%6,%7}, {%8,%9}, {%0,%1,%2,%3};" \
        : "+f"((c)[0]), "+f"((c)[1]), "+f"((c)[2]), "+f"((c)[3]) \
        : "r"((a)[0]), "r"((a)[1]), "r"((a)[2]), "r"((a)[3]), "r"(b0_), "r"(b1_))

__device__ __forceinline__ int getlab(const void* lab, int i, int is64) {
    if (is64) return (int)((const long long*)lab)[i];
    return ((const int*)lab)[i];
}
__device__ __forceinline__ bool keybetter(float av, int ai, float bv, int bi) {
    return (av > bv) || (av == bv && ai < bi);
}
__device__ __forceinline__ uint32_t sw128(uint32_t off) { return off ^ ((off >> 3) & 0x70u); }

__device__ __forceinline__ void merge2(float& v1, int& i1, float& v2, int& i2,
                                       float o1v, int o1i, float o2v, int o2i) {
    if (keybetter(o1v, o1i, v1, i1)) {
        if (keybetter(v1, i1, o2v, o2i)) { v2 = v1; i2 = i1; }
        else                             { v2 = o2v; i2 = o2i; }
        v1 = o1v; i1 = o1i;
    } else if (keybetter(o1v, o1i, v2, i2)) { v2 = o1v; i2 = o1i; }
}

// ---------------- kernel 1: fused detect + norms + fp16 convert ----------------
__global__ void k_prep(const float* __restrict__ emb, const float* __restrict__ clot,
                       const void* __restrict__ lab) {
    int r = blockIdx.x, t = threadIdx.x;
    int lane = t & 31, w = t >> 5;
    if (r == 0 && t == 0) {
        const unsigned* p = (const unsigned*)lab;
        int is64 = 1;
        for (int i = 0; i < 64; i++) if (p[2 * i + 1] != 0u) { is64 = 0; break; }
        g_lab64 = is64;
    }
    float4 v = ((const float4*)(emb + (size_t)r * DIM))[t];
    float s = v.x * v.x + v.y * v.y + v.z * v.z + v.w * v.w;
    size_t o = (size_t)r * DIM + t * 4;
    *(__half2*)(g_hi + o)     = __half2(__float2half(v.x), __float2half(v.y));
    *(__half2*)(g_hi + o + 2) = __half2(__float2half(v.z), __float2half(v.w));
    float c = 0.f;
    if (t < DIM2 / 4) {
        float4 wv = ((const float4*)(clot + (size_t)r * DIM2))[t];
        c = wv.x * wv.x + wv.y * wv.y + wv.z * wv.z + wv.w * wv.w;
    }
    #pragma unroll
    for (int o2 = 16; o2 > 0; o2 >>= 1) {
        s += __shfl_xor_sync(0xffffffffu, s, o2);
        c += __shfl_xor_sync(0xffffffffu, c, o2);
    }
    __shared__ float se[8], sc[8];
    if (lane == 0) { se[w] = s; sc[w] = c; }
    __syncthreads();
    if (t == 0) {
        float ss = 0.f, cc = 0.f;
        #pragma unroll
        for (int i = 0; i < 8; i++) { ss += se[i]; cc += sc[i]; }
        g_sq[r] = ss; g_nrm[r] = sqrtf(cc);
    }
}

// ---------------- kernel 2: fp16 HMMA GEMM ----------------
// ids [0,2016): full 128x128 off-diag tiles (row+col harvest).
// ids [2016,2144): diagonal tiles split into 64-row halves (row harvest only).
__global__ __launch_bounds__(256, 2) void k_dist_mma(const void* __restrict__ lab) {
    extern __shared__ char smem[];
    const uint32_t sb = smem_u32(smem);
    const int tid = threadIdx.x;
    const int lane = tid & 31, wid = tid >> 5;
    const int lab64 = g_lab64;
    const int tg = lane & 3, g = lane >> 2;
    const int krot = wid & 3;

    if (blockIdx.x >= NOFFD) {
        // ================= diagonal half-tile path (BM=64 x BN=128) =================
        int u = blockIdx.x - NOFFD;      // 0..127
        int b = u >> 1, h = u & 1;
        const int r0h = b * 128 + h * 64;
        const int c0 = b * 128;
        const int wm = wid >> 1, wn = wid & 1;   // 4 x 2 warps, 16row x 64col tiles

        const char* srcp[6];
        uint32_t dsto[6];
        #pragma unroll
        for (int v = 0; v < 2; v++) {
            int i = tid + v * 256;
            int row = i >> 3, seg = i & 7;
            srcp[v] = (const char*)(g_hi + (size_t)(r0h + row) * DIM + seg * 8);
            dsto[v] = sw128((uint32_t)row * 128u + (uint32_t)seg * 16u);
        }
        #pragma unroll
        for (int v = 2; v < 6; v++) {
            int j = tid + (v - 2) * 256;
            int row = j >> 3, seg = j & 7;
            srcp[v] = (const char*)(g_hi + (size_t)(c0 + row) * DIM + seg * 8);
            dsto[v] = B_OFF + sw128((uint32_t)row * 128u + (uint32_t)seg * 16u);
        }

        uint32_t preA, mskA, preB[4], mskB[4];
        {
            int rA = wm * 16 + (lane & 15);
            int sA = lane >> 4;
            uint32_t p = (uint32_t)rA * 128u + (uint32_t)sA * 16u;
            mskA = (p >> 3) & 0x70u; preA = p;
            int rB = wn * 64 + ((lane >> 4) << 3) + (lane & 7);
            int sB = (lane >> 3) & 1;
            #pragma unroll
            for (int np = 0; np < 4; np++) {
                uint32_t q = (uint32_t)(rB + np * 16) * 128u + (uint32_t)sB * 16u;
                mskB[np] = (q >> 3) & 0x70u; preB[np] = q;
            }
        }

        float acc[8][4];
        #pragma unroll
        for (int a = 0; a < 8; a++)
            #pragma unroll
            for (int c = 0; c < 4; c++) acc[a][c] = 0.f;

        #pragma unroll
        for (int p = 0; p < 2; p++) {
            uint32_t db = sb + (uint32_t)p * STAGE_BYTES;
            #pragma unroll
            for (int v = 0; v < 6; v++) cpasync16(db + dsto[v], srcp[v] + (size_t)p * 128);
            CP_COMMIT();
        }
        int buf = 0, pbuf = 2;
        for (int s = 0; s < NSTAGES_K; s++) {
            CP_WAIT1();
            __syncthreads();
            {
                int sn = s + 2;
                if (sn < NSTAGES_K) {
                    uint32_t db = sb + (uint32_t)pbuf * STAGE_BYTES;
                    #pragma unroll
                    for (int v = 0; v < 6; v++) cpasync16(db + dsto[v], srcp[v] + (size_t)sn * 128);
                }
                CP_COMMIT();
            }
            const uint32_t base = sb + (uint32_t)buf * STAGE_BYTES;
            const uint32_t baseB = base + B_OFF;
            if (++buf == NSTG) buf = 0;
            if (++pbuf == NSTG) pbuf = 0;

            #pragma unroll
            for (int kci = 0; kci < 4; kci++) {
                const int kc = (kci + krot) & 3;
                const uint32_t kd = (uint32_t)kc * 32u;
                uint32_t BH[4][4];
                #pragma unroll
                for (int np = 0; np < 4; np++)
                    LDM4(BH[np], baseB + ((preB[np] + kd) ^ mskB[np]));
                uint32_t AH[4];
                LDM4(AH, base + ((preA + kd) ^ mskA));
                #pragma unroll
                for (int nt = 0; nt < 8; nt++)
                    MMA16816(acc[nt], AH, BH[nt >> 1][(nt & 1) * 2], BH[nt >> 1][(nt & 1) * 2 + 1]);
            }
        }

        float sqj[16]; int labj[16];
        #pragma unroll
        for (int ln = 0; ln < 16; ln++) {
            int cc = c0 + wn * 64 + (ln >> 1) * 8 + tg * 2 + (ln & 1);
            sqj[ln] = g_sq[cc];
            labj[ln] = getlab(lab, cc, lab64);
        }
        float sqi[2]; int labi[2];
        #pragma unroll
        for (int lm = 0; lm < 2; lm++) {
            int m = r0h + wm * 16 + g + lm * 8;
            sqi[lm] = g_sq[m];
            labi[lm] = getlab(lab, m, lab64);
        }
        CP_WAIT0();
        __syncthreads();

        float* sv1 = (float*)smem;            // [64][2]
        float* sv2 = (float*)(smem + 512);
        float* smn = (float*)(smem + 1024);
        int*   si1 = (int*)(smem + 1536);
        int*   si2 = (int*)(smem + 2048);

        float b1v[2], b2v[2], mnv[2]; int b1i[2], b2i[2];
        #pragma unroll
        for (int lm = 0; lm < 2; lm++) {
            float v1 = -INFINITY, v2 = -INFINITY, mn = INFINITY;
            int i1 = 0x7fffffff, i2 = 0x7fffffff;
            #pragma unroll
            for (int ln = 0; ln < 16; ln++) {
                int col = c0 + wn * 64 + (ln >> 1) * 8 + tg * 2 + (ln & 1);
                float d2 = fmaf(-2.0f, acc[ln >> 1][lm * 2 + (ln & 1)], sqi[lm] + sqj[ln]);
                bool same = (labi[lm] == labj[ln]);
                float pv = same ? d2 : d2 - BIGF;
                float nv = same ? d2 + BIGF : d2;
                mn = fminf(mn, nv);
                if (keybetter(pv, col, v1, i1)) { v2 = v1; i2 = i1; v1 = pv; i1 = col; }
                else if (keybetter(pv, col, v2, i2)) { v2 = pv; i2 = col; }
            }
            b1v[lm] = v1; b1i[lm] = i1; b2v[lm] = v2; b2i[lm] = i2; mnv[lm] = mn;
        }
        #pragma unroll
        for (int lm = 0; lm < 2; lm++) {
            #pragma unroll
            for (int off = 1; off <= 2; off <<= 1) {
                float o1v = __shfl_xor_sync(0xffffffffu, b1v[lm], off);
                int   o1i = __shfl_xor_sync(0xffffffffu, b1i[lm], off);
                float o2v = __shfl_xor_sync(0xffffffffu, b2v[lm], off);
                int   o2i = __shfl_xor_sync(0xffffffffu, b2i[lm], off);
                float omn = __shfl_xor_sync(0xffffffffu, mnv[lm], off);
                mnv[lm] = fminf(mnv[lm], omn);
                merge2(b1v[lm], b1i[lm], b2v[lm], b2i[lm], o1v, o1i, o2v, o2i);
            }
        }
        if (tg == 0) {
            #pragma unroll
            for (int lm = 0; lm < 2; lm++) {
                int rl = wm * 16 + g + lm * 8;
                sv1[rl * 2 + wn] = b1v[lm]; si1[rl * 2 + wn] = b1i[lm];
                sv2[rl * 2 + wn] = b2v[lm]; si2[rl * 2 + wn] = b2i[lm];
                smn[rl * 2 + wn] = mnv[lm];
            }
        }
        __syncthreads();
        if (tid < 64) {
            float v1 = -INFINITY, v2 = -INFINITY, mn = INFINITY;
            int i1 = 0x7fffffff, i2 = 0x7fffffff;
            #pragma unroll
            for (int w = 0; w < 2; w++) {
                mn = fminf(mn, smn[tid * 2 + w]);
                merge2(v1, i1, v2, i2, sv1[tid * 2 + w], si1[tid * 2 + w], sv2[tid * 2 + w], si2[tid * 2 + w]);
            }
            int r = r0h + tid;
            g_p1v[b][r] = v1; g_p1i[b][r] = i1;
            g_p2v[b][r] = v2; g_p2i[b][r] = i2;
            g_pmn[b][r] = mn;
        }
        return;
    }

    // ================= full off-diagonal tile path =================
    const int wm = wid >> 2, wn = wid & 3;
    int rb, cb;
    {
        int u = blockIdx.x; rb = 0;
        while (u >= 63 - rb) { u -= 63 - rb; rb++; }
        cb = rb + 1 + u;
    }
    const int r0 = rb * BM, c0 = cb * BN;

    const char* srcp[8];
    uint32_t dsto[8];
    #pragma unroll
    for (int v = 0; v < 4; v++) {
        int i = tid + v * 256;
        int row = i >> 3, seg = i & 7;
        srcp[v] = (const char*)(g_hi + (size_t)(r0 + row) * DIM + seg * 8);
        dsto[v] = sw128((uint32_t)row * 128u + (uint32_t)seg * 16u);
    }
    #pragma unroll
    for (int v = 4; v < 8; v++) {
        int j = tid + (v - 4) * 256;
        int row = j >> 3, seg = j & 7;
        srcp[v] = (const char*)(g_hi + (size_t)(c0 + row) * DIM + seg * 8);
        dsto[v] = B_OFF + sw128((uint32_t)row * 128u + (uint32_t)seg * 16u);
    }

    uint32_t preA[4], mskA[4], preB[2], mskB[2];
    {
        int rA = wm * 64 + (lane & 15);
        int sA = lane >> 4;
        #pragma unroll
        for (int mt = 0; mt < 4; mt++) {
            uint32_t p = (uint32_t)(rA + mt * 16) * 128u + (uint32_t)sA * 16u;
            mskA[mt] = (p >> 3) & 0x70u;
            preA[mt] = p;
        }
        int rB = wn * 32 + ((lane >> 4) << 3) + (lane & 7);
        int sB = (lane >> 3) & 1;
        #pragma unroll
        for (int np = 0; np < 2; np++) {
            uint32_t p = (uint32_t)(rB + np * 16) * 128u + (uint32_t)sB * 16u;
            mskB[np] = (p >> 3) & 0x70u;
            preB[np] = p;
        }
    }

    float acc[4][4][4];
    #pragma unroll
    for (int a = 0; a < 4; a++)
        #pragma unroll
        for (int b2 = 0; b2 < 4; b2++)
            #pragma unroll
            for (int c = 0; c < 4; c++) acc[a][b2][c] = 0.f;

    #pragma unroll
    for (int p = 0; p < 2; p++) {
        uint32_t db = sb + (uint32_t)p * STAGE_BYTES;
        #pragma unroll
        for (int v = 0; v < 8; v++) cpasync16(db + dsto[v], srcp[v] + (size_t)p * 128);
        CP_COMMIT();
    }

    int buf = 0, pbuf = 2;
    for (int s = 0; s < NSTAGES_K; s++) {
        CP_WAIT1();
        __syncthreads();
        {
            int sn = s + 2;
            if (sn < NSTAGES_K) {
                uint32_t db = sb + (uint32_t)pbuf * STAGE_BYTES;
                #pragma unroll
                for (int v = 0; v < 8; v++) cpasync16(db + dsto[v], srcp[v] + (size_t)sn * 128);
            }
            CP_COMMIT();
        }
        const uint32_t base = sb + (uint32_t)buf * STAGE_BYTES;
        const uint32_t baseB = base + B_OFF;
        if (++buf == NSTG) buf = 0;
        if (++pbuf == NSTG) pbuf = 0;

        #pragma unroll
        for (int kci = 0; kci < 4; kci++) {
            const int kc = (kci + krot) & 3;
            const uint32_t kd = (uint32_t)kc * 32u;
            uint32_t BH[2][4];
            #pragma unroll
            for (int np = 0; np < 2; np++)
                LDM4(BH[np], baseB + ((preB[np] + kd) ^ mskB[np]));
            uint32_t AH[4][4];
            #pragma unroll
            for (int mt = 0; mt < 4; mt++)
                LDM4(AH[mt], base + ((preA[mt] + kd) ^ mskA[mt]));
            #pragma unroll
            for (int mt = 0; mt < 4; mt++)
                #pragma unroll
                for (int nt = 0; nt < 4; nt++)
                    MMA16816(acc[mt][nt], AH[mt], BH[nt >> 1][(nt & 1) * 2], BH[nt >> 1][(nt & 1) * 2 + 1]);
        }
    }

    float sqj[8]; int labj[8];
    #pragma unroll
    for (int ln = 0; ln < 8; ln++) {
        int cc = c0 + wn * 32 + (ln >> 1) * 8 + tg * 2 + (ln & 1);
        sqj[ln] = g_sq[cc];
        labj[ln] = getlab(lab, cc, lab64);
    }
    float sqi[8]; int labi[8];
    #pragma unroll
    for (int lm = 0; lm < 8; lm++) {
        int m = r0 + wm * 64 + (lm >> 1) * 16 + g + (lm & 1) * 8;
        sqi[lm] = g_sq[m];
        labi[lm] = getlab(lab, m, lab64);
    }

    CP_WAIT0();
    __syncthreads();

    float* sv1 = (float*)smem;              // [128][4]
    float* sv2 = (float*)(smem + 2048);
    float* smn = (float*)(smem + 4096);
    int*   si1 = (int*)(smem + 6144);
    int*   si2 = (int*)(smem + 8192);
    float* cv1 = (float*)(smem + 16384);    // [128][2]
    float* cv2 = (float*)(smem + 17408);
    float* cmn = (float*)(smem + 18432);
    int*   ci1 = (int*)(smem + 19456);
    int*   ci2 = (int*)(smem + 20480);

    {
        float b1v[8], b2v[8], mnv[8]; int b1i[8], b2i[8];
        #pragma unroll
        for (int lm = 0; lm < 8; lm++) {
            float v1 = -INFINITY, v2 = -INFINITY, mn = INFINITY;
            int i1 = 0x7fffffff, i2 = 0x7fffffff;
            #pragma unroll
            for (int ln = 0; ln < 8; ln++) {
                int col = c0 + wn * 32 + (ln >> 1) * 8 + tg * 2 + (ln & 1);
                float& ar = acc[lm >> 1][ln >> 1][(lm & 1) * 2 + (ln & 1)];
                float d2 = fmaf(-2.0f, ar, sqi[lm] + sqj[ln]);
                ar = d2;
                bool same = (labi[lm] == labj[ln]);
                float pv = same ? d2 : d2 - BIGF;
                float nv = same ? d2 + BIGF : d2;
                mn = fminf(mn, nv);
                if (keybetter(pv, col, v1, i1)) { v2 = v1; i2 = i1; v1 = pv; i1 = col; }
                else if (keybetter(pv, col, v2, i2)) { v2 = pv; i2 = col; }
            }
            b1v[lm] = v1; b1i[lm] = i1; b2v[lm] = v2; b2i[lm] = i2; mnv[lm] = mn;
        }
        #pragma unroll
        for (int lm = 0; lm < 8; lm++) {
            #pragma unroll
            for (int off = 1; off <= 2; off <<= 1) {
                float o1v = __shfl_xor_sync(0xffffffffu, b1v[lm], off);
                int   o1i = __shfl_xor_sync(0xffffffffu, b1i[lm], off);
                float o2v = __shfl_xor_sync(0xffffffffu, b2v[lm], off);
                int   o2i = __shfl_xor_sync(0xffffffffu, b2i[lm], off);
                float omn = __shfl_xor_sync(0xffffffffu, mnv[lm], off);
                mnv[lm] = fminf(mnv[lm], omn);
                merge2(b1v[lm], b1i[lm], b2v[lm], b2i[lm], o1v, o1i, o2v, o2i);
            }
        }
        if (tg == 0) {
            #pragma unroll
            for (int lm = 0; lm < 8; lm++) {
                int rl = wm * 64 + (lm >> 1) * 16 + g + (lm & 1) * 8;
                sv1[rl * 4 + wn] = b1v[lm]; si1[rl * 4 + wn] = b1i[lm];
                sv2[rl * 4 + wn] = b2v[lm]; si2[rl * 4 + wn] = b2i[lm];
                smn[rl * 4 + wn] = mnv[lm];
            }
        }
    }

    {
        float b1v[8], b2v[8], mnv[8]; int b1i[8], b2i[8];
        #pragma unroll
        for (int ln = 0; ln < 8; ln++) {
            float v1 = -INFINITY, v2 = -INFINITY, mn = INFINITY;
            int i1 = 0x7fffffff, i2 = 0x7fffffff;
            #pragma unroll
            for (int lm = 0; lm < 8; lm++) {
                int rowidx = r0 + wm * 64 + (lm >> 1) * 16 + g + (lm & 1) * 8;
                float d2 = acc[lm >> 1][ln >> 1][(lm & 1) * 2 + (ln & 1)];
                bool same = (labi[lm] == labj[ln]);
                float pv = same ? d2 : d2 - BIGF;
                float nv = same ? d2 + BIGF : d2;
                mn = fminf(mn, nv);
                if (keybetter(pv, rowidx, v1, i1)) { v2 = v1; i2 = i1; v1 = pv; i1 = rowidx; }
                else if (keybetter(pv, rowidx, v2, i2)) { v2 = pv; i2 = rowidx; }
            }
            b1v[ln] = v1; b1i[ln] = i1; b2v[ln] = v2; b2i[ln] = i2; mnv[ln] = mn;
        }
        #pragma unroll
        for (int ln = 0; ln < 8; ln++) {
            #pragma unroll
            for (int off = 4; off <= 16; off <<= 1) {
                float o1v = __shfl_xor_sync(0xffffffffu, b1v[ln], off);
                int   o1i = __shfl_xor_sync(0xffffffffu, b1i[ln], off);
                float o2v = __shfl_xor_sync(0xffffffffu, b2v[ln], off);
                int   o2i = __shfl_xor_sync(0xffffffffu, b2i[ln], off);
                float omn = __shfl_xor_sync(0xffffffffu, mnv[ln], off);
                mnv[ln] = fminf(mnv[ln], omn);
                merge2(b1v[ln], b1i[ln], b2v[ln], b2i[ln], o1v, o1i, o2v, o2i);
            }
        }
        if (g == 0) {
            #pragma unroll
            for (int ln = 0; ln < 8; ln++) {
                int cl = wn * 32 + (ln >> 1) * 8 + tg * 2 + (ln & 1);
                cv1[cl * 2 + wm] = b1v[ln]; ci1[cl * 2 + wm] = b1i[ln];
                cv2[cl * 2 + wm] = b2v[ln]; ci2[cl * 2 + wm] = b2i[ln];
                cmn[cl * 2 + wm] = mnv[ln];
            }
        }
    }
    __syncthreads();

    if (tid < 128) {
        float v1 = -INFINITY, v2 = -INFINITY, mn = INFINITY;
        int i1 = 0x7fffffff, i2 = 0x7fffffff;
        #pragma unroll
        for (int w = 0; w < 4; w++) {
            mn = fminf(mn, smn[tid * 4 + w]);
            merge2(v1, i1, v2, i2, sv1[tid * 4 + w], si1[tid * 4 + w], sv2[tid * 4 + w], si2[tid * 4 + w]);
        }
        int r = r0 + tid;
        g_p1v[cb][r] = v1; g_p1i[cb][r] = i1;
        g_p2v[cb][r] = v2; g_p2i[cb][r] = i2;
        g_pmn[cb][r] = mn;
    } else {
        int t2 = tid - 128;
        float v1 = -INFINITY, v2 = -INFINITY, mn = INFINITY;
        int i1 = 0x7fffffff, i2 = 0x7fffffff;
        #pragma unroll
        for (int w = 0; w < 2; w++) {
            mn = fminf(mn, cmn[t2 * 2 + w]);
            merge2(v1, i1, v2, i2, cv1[t2 * 2 + w], ci1[t2 * 2 + w], cv2[t2 * 2 + w], ci2[t2 * 2 + w]);
        }
        int r = c0 + t2;
        g_p1v[rb][r] = v1; g_p1i[rb][r] = i1;
        g_p2v[rb][r] = v2; g_p2i[rb][r] = i2;
        g_pmn[rb][r] = mn;
    }
}

// ---------------- kernel 3: fused merge + alpha + loss-term partials ----------------
// one warp per row (8 rows/block); block writes a single 3-term partial.
__global__ void k_merge_alpha(const float* __restrict__ clot) {
    int t = threadIdx.x;
    int wrow = t >> 5;
    int r = blockIdx.x * 8 + wrow;
    int l = t & 31;
    float b1v = g_p1v[l][r]; int b1i = g_p1i[l][r];
    float b2v = g_p2v[l][r]; int b2i = g_p2i[l][r];
    float mn  = g_pmn[l][r];
    int c2 = l + 32;
    mn = fminf(mn, g_pmn[c2][r]);
    merge2(b1v, b1i, b2v, b2i, g_p1v[c2][r], g_p1i[c2][r], g_p2v[c2][r], g_p2i[c2][r]);
    #pragma unroll
    for (int off = 16; off > 0; off >>= 1) {
        float o1v = __shfl_xor_sync(0xffffffffu, b1v, off);
        int   o1i = __shfl_xor_sync(0xffffffffu, b1i, off);
        float o2v = __shfl_xor_sync(0xffffffffu, b2v, off);
        int   o2i = __shfl_xor_sync(0xffffffffu, b2i, off);
        float omn = __shfl_xor_sync(0xffffffffu, mn,  off);
        mn = fminf(mn, omn);
        merge2(b1v, b1i, b2v, b2i, o1v, o1i, o2v, o2i);
    }
    int j1 = b1i, j2 = b2i;
    const float* cr = clot + (size_t)r * DIM2;
    const float* ca = clot + (size_t)j1 * DIM2;
    const float* cb = clot + (size_t)j2 * DIM2;
    float d1 = 0.f, d2 = 0.f;
    #pragma unroll 4
    for (int k = l; k < DIM2; k += 32) {
        float c = cr[k];
        d1 = fmaf(c, ca[k], d1);
        d2 = fmaf(c, cb[k], d2);
    }
    #pragma unroll
    for (int o = 16; o > 0; o >>= 1) {
        d1 += __shfl_xor_sync(0xffffffffu, d1, o);
        d2 += __shfl_xor_sync(0xffffffffu, d2, o);
    }
    __shared__ float s1[8], s2[8], s3[8];
    if (l == 0) {
        float ap1 = (b1v < -1e6f) ? (sqrtf(fmaxf(b1v + BIGF, 1e-12f)) - BIGF)
                                  : sqrtf(fmaxf(b1v, 1e-12f));
        float ap2 = (b2v < -1e6f) ? (sqrtf(fmaxf(b2v + BIGF, 1e-12f)) - BIGF)
                                  : sqrtf(fmaxf(b2v, 1e-12f));
        float an  = (mn > 1e6f) ? (sqrtf(fmaxf(mn - BIGF, 1e-12f)) + BIGF)
                                : sqrtf(fmaxf(mn, 1e-12f));
        float a1 = d1 / (g_nrm[r] * g_nrm[j1]);
        float a2 = d2 / (g_nrm[r] * g_nrm[j2]);
        float y  = (a1 < a2) ? -1.f : 1.f;
        float ym = (a1 == a2) ? 0.f : 1.f;
        float x1 = ap2 * ym;
        float x2 = ap1 * ym + MARGINF * (a1 - a2 - y);
        float t11 = fmaxf(0.f, -y * (x1 - x2) + MARGINF);
        float ap1m = ap1 + MARGINF * (a1 - 1.f);
        float t13 = fmaxf(0.f, -(an - ap1m) + MARGINF);
        float tp = (an > ap1m) ? 1.f : 0.f;
        s1[wrow] = t11; s2[wrow] = t13; s3[wrow] = tp;
    }
    __syncthreads();
    if (t == 0) {
        float a = 0.f, b = 0.f, c = 0.f;
        #pragma unroll
        for (int i = 0; i < 8; i++) { a += s1[i]; b += s2[i]; c += s3[i]; }
        g_fin[blockIdx.x][0] = a;
        g_fin[blockIdx.x][1] = b;
        g_fin[blockIdx.x][2] = c;
    }
}

// ---------------- kernel 4: combine 1024 partials ----------------
__global__ void k_final2(float* __restrict__ out) {
    int t = threadIdx.x;   // 1024 threads
    float a = g_fin[t][0], b = g_fin[t][1], c = g_fin[t][2];
    #pragma unroll
    for (int o = 16; o > 0; o >>= 1) {
        a += __shfl_xor_sync(0xffffffffu, a, o);
        b += __shfl_xor_sync(0xffffffffu, b, o);
        c += __shfl_xor_sync(0xffffffffu, c, o);
    }
    __shared__ float s1[32], s2[32], s3[32];
    int w = t >> 5, l = t & 31;
    if (l == 0) { s1[w] = a; s2[w] = b; s3[w] = c; }
    __syncthreads();
    if (w == 0) {
        float aa = s1[l], bb = s2[l], cc = s3[l];
        #pragma unroll
        for (int o = 16; o > 0; o >>= 1) {
            aa += __shfl_xor_sync(0xffffffffu, aa, o);
            bb += __shfl_xor_sync(0xffffffffu, bb, o);
            cc += __shfl_xor_sync(0xffffffffu, cc, o);
        }
        if (l == 0) {
            out[0] = 0.1f * (aa / (float)NROW) + (bb / (float)NROW);
            out[1] = cc / (float)NROW;
        }
    }
}

// ---------------- launch ----------------
extern "C" void kernel_launch(void* const* d_in, const int* in_sizes, int n_in,
                              void* d_out, int out_size) {
    const float* emb  = (const float*)d_in[0];
    const void*  lab  = d_in[1];
    const float* clot = (const float*)d_in[2];
    float* out = (float*)d_out;

    cudaFuncSetAttribute(k_dist_mma, cudaFuncAttributeMaxDynamicSharedMemorySize, SMEM_TOTAL);

    k_prep<<<NROW, 256>>>(emb, clot, lab);
    k_dist_mma<<<NGRID, 256, SMEM_TOTAL>>>(lab);
    k_merge_alpha<<<NROW / 8, 256>>>(clot);
    k_final2<<<1, 1024>>>(out);
}